// round 1
// baseline (speedup 1.0000x reference)
#include <cuda_runtime.h>
#include <math.h>

#define H 2048
#define NH 16
#define HD 128
#define SEQ 2048
#define BATCH 2
#define NQKV (H + 2*HD)   // 2304
#define SCALE 0.08838834764831843f  // 1/sqrt(128)

// Scratch (allocation-free rule: __device__ globals)
__device__ float g_qkv[(size_t)BATCH * SEQ * NQKV];   // ~37.7 MB
__device__ float g_attn[(size_t)BATCH * SEQ * H];     // ~33.5 MB

// ---------------------------------------------------------------------------
// Tiled SGEMM with bias: C[M,N] = A[M,K] @ B[K,N] + bias[N]
// BM=128, BN=128, BK=16, 256 threads, 8x8 per thread.
// Column mapping per thread: cols {4*tx..4*tx+3} and {64+4*tx..+3} so that
// quarter-warp float4 LDS covers all 32 banks (conflict-free B reads).
// ---------------------------------------------------------------------------
template<int N>
__global__ void __launch_bounds__(256) sgemm_bias(
    const float* __restrict__ A, const float* __restrict__ B,
    const float* __restrict__ bias, float* __restrict__ C, int K)
{
    __shared__ float As[16][128];   // transposed: As[k][m]
    __shared__ float Bs[16][128];

    const int tid = threadIdx.x;
    const int tx = tid & 15;        // 0..15 -> col groups
    const int ty = tid >> 4;        // 0..15 -> row groups (8 rows each)
    const int m0 = blockIdx.y * 128;
    const int n0 = blockIdx.x * 128;

    // global load mapping
    const int arow = tid >> 2;          // 0..63
    const int acol = (tid & 3) * 4;     // 0,4,8,12
    const int brow = tid >> 4;          // 0..15
    const int bcol = (tid & 15) * 4;    // 0..60

    const float* Aptr = A + (size_t)(m0 + arow) * K + acol;
    const float* Bptr = B + (size_t)brow * N + n0 + bcol;

    float acc[8][8];
    #pragma unroll
    for (int i = 0; i < 8; i++)
        #pragma unroll
        for (int j = 0; j < 8; j++) acc[i][j] = 0.f;

    for (int k0 = 0; k0 < K; k0 += 16) {
        float4 a0 = *(const float4*)(Aptr);
        float4 a1 = *(const float4*)(Aptr + (size_t)64 * K);
        float4 b0 = *(const float4*)(Bptr);
        float4 b1 = *(const float4*)(Bptr + 64);
        __syncthreads();
        As[acol + 0][arow] = a0.x;  As[acol + 1][arow] = a0.y;
        As[acol + 2][arow] = a0.z;  As[acol + 3][arow] = a0.w;
        As[acol + 0][arow + 64] = a1.x;  As[acol + 1][arow + 64] = a1.y;
        As[acol + 2][arow + 64] = a1.z;  As[acol + 3][arow + 64] = a1.w;
        *(float4*)&Bs[brow][bcol]      = b0;
        *(float4*)&Bs[brow][bcol + 64] = b1;
        __syncthreads();

        #pragma unroll
        for (int k = 0; k < 16; k++) {
            float4 av0 = *(float4*)&As[k][ty * 8];
            float4 av1 = *(float4*)&As[k][ty * 8 + 4];
            float4 bv0 = *(float4*)&Bs[k][tx * 4];
            float4 bv1 = *(float4*)&Bs[k][64 + tx * 4];
            float a[8] = {av0.x, av0.y, av0.z, av0.w, av1.x, av1.y, av1.z, av1.w};
            float b[8] = {bv0.x, bv0.y, bv0.z, bv0.w, bv1.x, bv1.y, bv1.z, bv1.w};
            #pragma unroll
            for (int i = 0; i < 8; i++)
                #pragma unroll
                for (int j = 0; j < 8; j++)
                    acc[i][j] += a[i] * b[j];
        }
        Aptr += 16;
        Bptr += (size_t)16 * N;
    }

    // epilogue: bias + store (two float4s per row)
    const int c0 = n0 + tx * 4;
    const int c1 = n0 + 64 + tx * 4;
    float4 bias0 = *(const float4*)(bias + c0);
    float4 bias1 = *(const float4*)(bias + c1);
    #pragma unroll
    for (int i = 0; i < 8; i++) {
        int row = m0 + ty * 8 + i;
        float4 r0 = {acc[i][0] + bias0.x, acc[i][1] + bias0.y,
                     acc[i][2] + bias0.z, acc[i][3] + bias0.w};
        float4 r1 = {acc[i][4] + bias1.x, acc[i][5] + bias1.y,
                     acc[i][6] + bias1.z, acc[i][7] + bias1.w};
        *(float4*)(C + (size_t)row * N + c0) = r0;
        *(float4*)(C + (size_t)row * N + c1) = r1;
    }
}

// ---------------------------------------------------------------------------
// Causal MQA flash attention (fp32, online softmax).
// grid (SEQ/64, NH, BATCH), 256 threads. BQ=64 q-rows, BK=32 k-rows per tile.
// Q/K padded to 132 floats/row: K float4 reads span all 32 banks per
// quarter-warp (stride 528B -> conflict-free).
// ---------------------------------------------------------------------------
#define QPAD 132
#define PPAD 33
#define ATTN_SMEM_BYTES ((64*QPAD + 32*QPAD + 32*QPAD + 64*PPAD + 3*64) * 4)

__global__ void __launch_bounds__(256) mqa_attn(
    const float* __restrict__ qkv, float* __restrict__ out)
{
    extern __shared__ float smem[];
    float (*Qs)[QPAD] = (float(*)[QPAD])smem;                       // 64 x 132
    float (*Ks)[QPAD] = (float(*)[QPAD])(smem + 64 * QPAD);         // 32 x 132
    float (*Vs)[QPAD] = (float(*)[QPAD])(smem + (64 + 32) * QPAD);  // 32 x 132
    float (*Ps)[PPAD] = (float(*)[PPAD])(smem + (64 + 64) * QPAD);  // 64 x 33
    float* m_s = smem + (64 + 64) * QPAD + 64 * PPAD;
    float* l_s = m_s + 64;
    float* f_s = l_s + 64;

    const int tid  = threadIdx.x;
    const int warp = tid >> 5, lane = tid & 31;
    const int oy = tid >> 4, ox = tid & 15;
    const int qt = blockIdx.x, h = blockIdx.y, b = blockIdx.z;
    const int q0 = qt * 64;

    const float* qbase = qkv + (size_t)b * SEQ * NQKV + h * HD;
    const float* kbase = qkv + (size_t)b * SEQ * NQKV + H;
    const float* vbase = kbase + HD;

    // Load Q tile (64 rows x 128, row stride NQKV)
    for (int i = tid; i < 64 * 32; i += 256) {
        int r = i >> 5, c4 = (i & 31) * 4;
        *(float4*)&Qs[r][c4] = *(const float4*)(qbase + (size_t)(q0 + r) * NQKV + c4);
    }
    if (tid < 64) { m_s[tid] = -1e30f; l_s[tid] = 0.f; }

    float o[4][8];
    #pragma unroll
    for (int i = 0; i < 4; i++)
        #pragma unroll
        for (int j = 0; j < 8; j++) o[i][j] = 0.f;

    const int nkt = qt * 2 + 2;   // causal: k tiles 0..(q0+63)/32
    __syncthreads();

    for (int kt = 0; kt < nkt; kt++) {
        const int k0 = kt * 32;
        // load K,V tiles (32 x 128 each)
        for (int i = tid; i < 32 * 32; i += 256) {
            int r = i >> 5, c4 = (i & 31) * 4;
            *(float4*)&Ks[r][c4] = *(const float4*)(kbase + (size_t)(k0 + r) * NQKV + c4);
            *(float4*)&Vs[r][c4] = *(const float4*)(vbase + (size_t)(k0 + r) * NQKV + c4);
        }
        __syncthreads();

        // S phase: warp -> rows 8*warp..+7, lane -> col = lane
        float acc[8];
        #pragma unroll
        for (int i = 0; i < 8; i++) acc[i] = 0.f;
        #pragma unroll 4
        for (int d = 0; d < 128; d += 4) {
            float4 kv = *(float4*)&Ks[lane][d];
            #pragma unroll
            for (int i = 0; i < 8; i++) {
                float4 qv = *(float4*)&Qs[8 * warp + i][d];
                acc[i] += qv.x * kv.x + qv.y * kv.y + qv.z * kv.z + qv.w * kv.w;
            }
        }
        #pragma unroll
        for (int i = 0; i < 8; i++) {
            int qi = q0 + 8 * warp + i, ki = k0 + lane;
            Ps[8 * warp + i][lane] = (ki <= qi) ? acc[i] * SCALE : -1e30f;
        }
        __syncthreads();

        // online softmax: one thread per row
        if (tid < 64) {
            float mold = m_s[tid];
            float mx = mold;
            #pragma unroll 8
            for (int c = 0; c < 32; c++) mx = fmaxf(mx, Ps[tid][c]);
            float f = __expf(mold - mx);
            float sum = 0.f;
            #pragma unroll 8
            for (int c = 0; c < 32; c++) {
                float p = __expf(Ps[tid][c] - mx);
                Ps[tid][c] = p;
                sum += p;
            }
            l_s[tid] = l_s[tid] * f + sum;
            m_s[tid] = mx;
            f_s[tid] = f;
        }
        __syncthreads();

        // PV: thread -> rows 4*oy..+3, cols {4*ox..+3, 64+4*ox..+3}
        #pragma unroll
        for (int i = 0; i < 4; i++) {
            float f = f_s[4 * oy + i];
            #pragma unroll
            for (int j = 0; j < 8; j++) o[i][j] *= f;
        }
        #pragma unroll 4
        for (int k = 0; k < 32; k++) {
            float4 v0 = *(float4*)&Vs[k][4 * ox];
            float4 v1 = *(float4*)&Vs[k][64 + 4 * ox];
            #pragma unroll
            for (int i = 0; i < 4; i++) {
                float p = Ps[4 * oy + i][k];
                o[i][0] += p * v0.x;  o[i][1] += p * v0.y;
                o[i][2] += p * v0.z;  o[i][3] += p * v0.w;
                o[i][4] += p * v1.x;  o[i][5] += p * v1.y;
                o[i][6] += p * v1.z;  o[i][7] += p * v1.w;
            }
        }
        __syncthreads();
    }

    // write out (divide by running denom)
    #pragma unroll
    for (int i = 0; i < 4; i++) {
        int r = 4 * oy + i;
        float inv = 1.f / l_s[r];
        size_t row = (size_t)(b * SEQ + q0 + r) * H + h * HD;
        float4 r0 = {o[i][0] * inv, o[i][1] * inv, o[i][2] * inv, o[i][3] * inv};
        float4 r1 = {o[i][4] * inv, o[i][5] * inv, o[i][6] * inv, o[i][7] * inv};
        *(float4*)(out + row + 4 * ox)      = r0;
        *(float4*)(out + row + 64 + 4 * ox) = r1;
    }
}

// ---------------------------------------------------------------------------

extern "C" void kernel_launch(void* const* d_in, const int* in_sizes, int n_in,
                              void* d_out, int out_size)
{
    (void)in_sizes; (void)n_in; (void)out_size;
    const float* x     = (const float*)d_in[0];
    const float* Wqkv  = (const float*)d_in[1];
    const float* bqkv  = (const float*)d_in[2];
    const float* Wproj = (const float*)d_in[3];
    const float* bproj = (const float*)d_in[4];
    float* out = (float*)d_out;

    float *qkv_ptr, *attn_ptr;
    cudaGetSymbolAddress((void**)&qkv_ptr, g_qkv);
    cudaGetSymbolAddress((void**)&attn_ptr, g_attn);

    cudaFuncSetAttribute(mqa_attn, cudaFuncAttributeMaxDynamicSharedMemorySize,
                         ATTN_SMEM_BYTES);

    // 1) QKV GEMM: [4096,2048] @ [2048,2304] + bias
    sgemm_bias<NQKV><<<dim3(NQKV / 128, (BATCH * SEQ) / 128), 256>>>(
        x, Wqkv, bqkv, qkv_ptr, H);

    // 2) causal MQA flash attention -> g_attn [4096, 2048]
    mqa_attn<<<dim3(SEQ / 64, NH, BATCH), 256, ATTN_SMEM_BYTES>>>(qkv_ptr, attn_ptr);

    // 3) proj GEMM: [4096,2048] @ [2048,2048] + bias -> d_out
    sgemm_bias<H><<<dim3(H / 128, (BATCH * SEQ) / 128), 256>>>(
        attn_ptr, Wproj, bproj, out, H);
}

// round 2
// speedup vs baseline: 1.5467x; 1.5467x over previous
#include <cuda_runtime.h>
#include <math.h>
#include <stdint.h>

#define H 2048
#define NH 16
#define HD 128
#define SEQ 2048
#define BATCH 2
#define NQKV (H + 2*HD)   // 2304
#define SCALE 0.08838834764831843f  // 1/sqrt(128)

// Scratch (allocation-free rule: __device__ globals)
__device__ float g_qkv[(size_t)BATCH * SEQ * NQKV];   // ~37.7 MB
__device__ float g_attn[(size_t)BATCH * SEQ * H];     // ~33.5 MB

// ---------------------------------------------------------------------------
// TF32 tensor-core GEMM with bias: C[M,N] = A[M,K] @ B[K,N] + bias[N]
// BM=128, BN=128, BK=32, 256 threads (8 warps as 2x4), mma.sync.m16n8k8 tf32.
// Warp computes 64x32 via 4x4 grid of 16x8 mma tiles.
// Smem: As[128][36] (stride 36 == 4 mod 32 -> a-frag loads conflict-free),
//       Bs[32][136]  (stride 136 == 8 mod 32 -> b-frag loads conflict-free).
// ---------------------------------------------------------------------------
__device__ __forceinline__ uint32_t f2tf32(float x) {
    uint32_t r;
    asm("cvt.rna.tf32.f32 %0, %1;" : "=r"(r) : "f"(x));
    return r;
}

template<int N>
__global__ void __launch_bounds__(256) gemm_tf32(
    const float* __restrict__ A, const float* __restrict__ B,
    const float* __restrict__ bias, float* __restrict__ C, int K)
{
    __shared__ uint32_t As[128][36];
    __shared__ uint32_t Bs[32][136];

    const int tid  = threadIdx.x;
    const int warp = tid >> 5, lane = tid & 31;
    const int wm = warp >> 2, wn = warp & 3;     // warp grid 2 x 4
    const int g  = lane >> 2, tg = lane & 3;     // groupID, threadInGroup
    const int m0 = blockIdx.y * 128;
    const int n0 = blockIdx.x * 128;

    // global-load mappings
    const int ar  = tid >> 3;           // 0..31  (A row within 32-row chunk)
    const int ac4 = (tid & 7) * 4;      // 0..28  (A col, float4)
    const int bc4 = (tid & 31) * 4;     // 0..124 (B col, float4)
    const int br  = tid >> 5;           // 0..7   (B row within 8-row chunk)

    float acc[4][4][4];
    #pragma unroll
    for (int i = 0; i < 4; i++)
        #pragma unroll
        for (int j = 0; j < 4; j++)
            #pragma unroll
            for (int c = 0; c < 4; c++) acc[i][j][c] = 0.f;

    for (int kt = 0; kt < K; kt += 32) {
        __syncthreads();
        // A tile: 128 x 32 (row-major in smem, tf32-converted)
        #pragma unroll
        for (int i = 0; i < 4; i++) {
            float4 v = *(const float4*)(A + (size_t)(m0 + ar + 32*i) * K + kt + ac4);
            uint4 t = {f2tf32(v.x), f2tf32(v.y), f2tf32(v.z), f2tf32(v.w)};
            *(uint4*)&As[ar + 32*i][ac4] = t;
        }
        // B tile: 32 x 128
        #pragma unroll
        for (int i = 0; i < 4; i++) {
            float4 v = *(const float4*)(B + (size_t)(kt + br + 8*i) * N + n0 + bc4);
            uint4 t = {f2tf32(v.x), f2tf32(v.y), f2tf32(v.z), f2tf32(v.w)};
            *(uint4*)&Bs[br + 8*i][bc4] = t;
        }
        __syncthreads();

        #pragma unroll
        for (int ks = 0; ks < 4; ks++) {
            const int kb = ks * 8;
            uint32_t a[4][4], b[4][2];
            #pragma unroll
            for (int mt = 0; mt < 4; mt++) {
                const int mb = wm * 64 + mt * 16;
                a[mt][0] = As[mb + g    ][kb + tg    ];
                a[mt][1] = As[mb + g + 8][kb + tg    ];
                a[mt][2] = As[mb + g    ][kb + tg + 4];
                a[mt][3] = As[mb + g + 8][kb + tg + 4];
            }
            #pragma unroll
            for (int nt = 0; nt < 4; nt++) {
                const int nb = wn * 32 + nt * 8;
                b[nt][0] = Bs[kb + tg    ][nb + g];
                b[nt][1] = Bs[kb + tg + 4][nb + g];
            }
            #pragma unroll
            for (int mt = 0; mt < 4; mt++)
                #pragma unroll
                for (int nt = 0; nt < 4; nt++) {
                    asm volatile(
                        "mma.sync.aligned.m16n8k8.row.col.f32.tf32.tf32.f32 "
                        "{%0,%1,%2,%3}, {%4,%5,%6,%7}, {%8,%9}, {%0,%1,%2,%3};"
                        : "+f"(acc[mt][nt][0]), "+f"(acc[mt][nt][1]),
                          "+f"(acc[mt][nt][2]), "+f"(acc[mt][nt][3])
                        : "r"(a[mt][0]), "r"(a[mt][1]), "r"(a[mt][2]), "r"(a[mt][3]),
                          "r"(b[nt][0]), "r"(b[nt][1]));
                }
        }
    }

    // epilogue: bias + store (float2 per half-tile row)
    #pragma unroll
    for (int nt = 0; nt < 4; nt++) {
        const int col = n0 + wn * 32 + nt * 8 + 2 * tg;
        float2 bv = *(const float2*)(bias + col);
        #pragma unroll
        for (int mt = 0; mt < 4; mt++) {
            const int row0 = m0 + wm * 64 + mt * 16 + g;
            float2 r0 = {acc[mt][nt][0] + bv.x, acc[mt][nt][1] + bv.y};
            float2 r1 = {acc[mt][nt][2] + bv.x, acc[mt][nt][3] + bv.y};
            *(float2*)(C + (size_t)row0 * N + col)       = r0;
            *(float2*)(C + (size_t)(row0 + 8) * N + col) = r1;
        }
    }
}

// ---------------------------------------------------------------------------
// Causal MQA flash attention (fp32, online softmax).
// grid (SEQ/64, NH, BATCH), 256 threads. BQ=64 q-rows, BK=32 k-rows per tile.
// ---------------------------------------------------------------------------
#define QPAD 132
#define PPAD 33
#define ATTN_SMEM_BYTES ((64*QPAD + 32*QPAD + 32*QPAD + 64*PPAD + 3*64) * 4)

__global__ void __launch_bounds__(256) mqa_attn(
    const float* __restrict__ qkv, float* __restrict__ out)
{
    extern __shared__ float smem[];
    float (*Qs)[QPAD] = (float(*)[QPAD])smem;                       // 64 x 132
    float (*Ks)[QPAD] = (float(*)[QPAD])(smem + 64 * QPAD);         // 32 x 132
    float (*Vs)[QPAD] = (float(*)[QPAD])(smem + (64 + 32) * QPAD);  // 32 x 132
    float (*Ps)[PPAD] = (float(*)[PPAD])(smem + (64 + 64) * QPAD);  // 64 x 33
    float* m_s = smem + (64 + 64) * QPAD + 64 * PPAD;
    float* l_s = m_s + 64;
    float* f_s = l_s + 64;

    const int tid  = threadIdx.x;
    const int warp = tid >> 5, lane = tid & 31;
    const int oy = tid >> 4, ox = tid & 15;
    const int qt = blockIdx.x, h = blockIdx.y, b = blockIdx.z;
    const int q0 = qt * 64;

    const float* qbase = qkv + (size_t)b * SEQ * NQKV + h * HD;
    const float* kbase = qkv + (size_t)b * SEQ * NQKV + H;
    const float* vbase = kbase + HD;

    // Load Q tile (64 rows x 128, row stride NQKV)
    for (int i = tid; i < 64 * 32; i += 256) {
        int r = i >> 5, c4 = (i & 31) * 4;
        *(float4*)&Qs[r][c4] = *(const float4*)(qbase + (size_t)(q0 + r) * NQKV + c4);
    }
    if (tid < 64) { m_s[tid] = -1e30f; l_s[tid] = 0.f; }

    float o[4][8];
    #pragma unroll
    for (int i = 0; i < 4; i++)
        #pragma unroll
        for (int j = 0; j < 8; j++) o[i][j] = 0.f;

    const int nkt = qt * 2 + 2;   // causal: k tiles 0..(q0+63)/32
    __syncthreads();

    for (int kt = 0; kt < nkt; kt++) {
        const int k0 = kt * 32;
        // load K,V tiles (32 x 128 each)
        for (int i = tid; i < 32 * 32; i += 256) {
            int r = i >> 5, c4 = (i & 31) * 4;
            *(float4*)&Ks[r][c4] = *(const float4*)(kbase + (size_t)(k0 + r) * NQKV + c4);
            *(float4*)&Vs[r][c4] = *(const float4*)(vbase + (size_t)(k0 + r) * NQKV + c4);
        }
        __syncthreads();

        // S phase: warp -> rows 8*warp..+7, lane -> col = lane
        float acc[8];
        #pragma unroll
        for (int i = 0; i < 8; i++) acc[i] = 0.f;
        #pragma unroll 4
        for (int d = 0; d < 128; d += 4) {
            float4 kv = *(float4*)&Ks[lane][d];
            #pragma unroll
            for (int i = 0; i < 8; i++) {
                float4 qv = *(float4*)&Qs[8 * warp + i][d];
                acc[i] += qv.x * kv.x + qv.y * kv.y + qv.z * kv.z + qv.w * kv.w;
            }
        }
        #pragma unroll
        for (int i = 0; i < 8; i++) {
            int qi = q0 + 8 * warp + i, ki = k0 + lane;
            Ps[8 * warp + i][lane] = (ki <= qi) ? acc[i] * SCALE : -1e30f;
        }
        __syncthreads();

        // online softmax: 4 threads per row, shfl reduction
        {
            const int row = tid >> 2;
            const int sub = tid & 3;
            float mold = m_s[row];
            float mx = -1e30f;
            #pragma unroll
            for (int c = 0; c < 8; c++) mx = fmaxf(mx, Ps[row][sub * 8 + c]);
            mx = fmaxf(mx, __shfl_xor_sync(0xffffffffu, mx, 1));
            mx = fmaxf(mx, __shfl_xor_sync(0xffffffffu, mx, 2));
            mx = fmaxf(mx, mold);
            float sum = 0.f;
            #pragma unroll
            for (int c = 0; c < 8; c++) {
                float p = __expf(Ps[row][sub * 8 + c] - mx);
                Ps[row][sub * 8 + c] = p;
                sum += p;
            }
            sum += __shfl_xor_sync(0xffffffffu, sum, 1);
            sum += __shfl_xor_sync(0xffffffffu, sum, 2);
            if (sub == 0) {
                float f = __expf(mold - mx);
                l_s[row] = l_s[row] * f + sum;
                m_s[row] = mx;
                f_s[row] = f;
            }
        }
        __syncthreads();

        // PV: thread -> rows 4*oy..+3, cols {4*ox..+3, 64+4*ox..+3}
        #pragma unroll
        for (int i = 0; i < 4; i++) {
            float f = f_s[4 * oy + i];
            #pragma unroll
            for (int j = 0; j < 8; j++) o[i][j] *= f;
        }
        #pragma unroll 4
        for (int k = 0; k < 32; k++) {
            float4 v0 = *(float4*)&Vs[k][4 * ox];
            float4 v1 = *(float4*)&Vs[k][64 + 4 * ox];
            #pragma unroll
            for (int i = 0; i < 4; i++) {
                float p = Ps[4 * oy + i][k];
                o[i][0] += p * v0.x;  o[i][1] += p * v0.y;
                o[i][2] += p * v0.z;  o[i][3] += p * v0.w;
                o[i][4] += p * v1.x;  o[i][5] += p * v1.y;
                o[i][6] += p * v1.z;  o[i][7] += p * v1.w;
            }
        }
        __syncthreads();
    }

    // write out (divide by running denom)
    #pragma unroll
    for (int i = 0; i < 4; i++) {
        int r = 4 * oy + i;
        float inv = 1.f / l_s[r];
        size_t row = (size_t)(b * SEQ + q0 + r) * H + h * HD;
        float4 r0 = {o[i][0] * inv, o[i][1] * inv, o[i][2] * inv, o[i][3] * inv};
        float4 r1 = {o[i][4] * inv, o[i][5] * inv, o[i][6] * inv, o[i][7] * inv};
        *(float4*)(out + row + 4 * ox)      = r0;
        *(float4*)(out + row + 64 + 4 * ox) = r1;
    }
}

// ---------------------------------------------------------------------------

extern "C" void kernel_launch(void* const* d_in, const int* in_sizes, int n_in,
                              void* d_out, int out_size)
{
    (void)in_sizes; (void)n_in; (void)out_size;
    const float* x     = (const float*)d_in[0];
    const float* Wqkv  = (const float*)d_in[1];
    const float* bqkv  = (const float*)d_in[2];
    const float* Wproj = (const float*)d_in[3];
    const float* bproj = (const float*)d_in[4];
    float* out = (float*)d_out;

    float *qkv_ptr, *attn_ptr;
    cudaGetSymbolAddress((void**)&qkv_ptr, g_qkv);
    cudaGetSymbolAddress((void**)&attn_ptr, g_attn);

    cudaFuncSetAttribute(mqa_attn, cudaFuncAttributeMaxDynamicSharedMemorySize,
                         ATTN_SMEM_BYTES);

    // 1) QKV GEMM: [4096,2048] @ [2048,2304] + bias (TF32 tensor cores)
    gemm_tf32<NQKV><<<dim3(NQKV / 128, (BATCH * SEQ) / 128), 256>>>(
        x, Wqkv, bqkv, qkv_ptr, H);

    // 2) causal MQA flash attention -> g_attn [4096, 2048]
    mqa_attn<<<dim3(SEQ / 64, NH, BATCH), 256, ATTN_SMEM_BYTES>>>(qkv_ptr, attn_ptr);

    // 3) proj GEMM: [4096,2048] @ [2048,2048] + bias (TF32 tensor cores)
    gemm_tf32<H><<<dim3(H / 128, (BATCH * SEQ) / 128), 256>>>(
        attn_ptr, Wproj, bproj, out, H);
}

// round 3
// speedup vs baseline: 2.1545x; 1.3930x over previous
#include <cuda_runtime.h>
#include <math.h>
#include <stdint.h>

#define H 2048
#define NH 16
#define HD 128
#define SEQ 2048
#define BATCH 2
#define NQKV (H + 2*HD)   // 2304
#define SCALE 0.08838834764831843f  // 1/sqrt(128)

// Scratch (allocation-free rule: __device__ globals)
__device__ float g_qkv[(size_t)BATCH * SEQ * NQKV];   // ~37.7 MB
__device__ float g_attn[(size_t)BATCH * SEQ * H];     // ~33.5 MB

__device__ __forceinline__ uint32_t f2tf32(float x) {
    uint32_t r;
    asm("cvt.rna.tf32.f32 %0, %1;" : "=r"(r) : "f"(x));
    return r;
}
__device__ __forceinline__ void split_tf32(float x, uint32_t& hi, uint32_t& lo) {
    asm("cvt.rna.tf32.f32 %0, %1;" : "=r"(hi) : "f"(x));
    float r = x - __uint_as_float(hi);
    asm("cvt.rna.tf32.f32 %0, %1;" : "=r"(lo) : "f"(r));
}
__device__ __forceinline__ void mma8(float* c, uint32_t a0, uint32_t a1,
                                     uint32_t a2, uint32_t a3,
                                     uint32_t b0, uint32_t b1) {
    asm volatile(
        "mma.sync.aligned.m16n8k8.row.col.f32.tf32.tf32.f32 "
        "{%0,%1,%2,%3}, {%4,%5,%6,%7}, {%8,%9}, {%0,%1,%2,%3};"
        : "+f"(c[0]), "+f"(c[1]), "+f"(c[2]), "+f"(c[3])
        : "r"(a0), "r"(a1), "r"(a2), "r"(a3), "r"(b0), "r"(b1));
}

// Fast exp on the FMA pipe (avoids the MUFU throughput floor).
// Valid for x <= 0 (flash-attn uses only non-positive args). ~1e-7 rel err.
__device__ __forceinline__ float fast_exp(float x) {
    float t = fmaxf(x * 1.4426950408889634f, -126.0f);
    float fl = floorf(t);
    float f = t - fl;
    float p =              1.535336188319500e-4f;
    p = fmaf(p, f, 1.339887440266574e-3f);
    p = fmaf(p, f, 9.618437357674640e-3f);
    p = fmaf(p, f, 5.550332471162809e-2f);
    p = fmaf(p, f, 2.402264791363012e-1f);
    p = fmaf(p, f, 6.931472028550421e-1f);
    p = fmaf(p, f, 1.0f);
    uint32_t sc = ((uint32_t)(int)(fl + 127.0f)) << 23;
    return p * __uint_as_float(sc);
}

// ---------------------------------------------------------------------------
// TF32 tensor-core GEMM with bias (unchanged from round 2).
// ---------------------------------------------------------------------------
template<int N>
__global__ void __launch_bounds__(256) gemm_tf32(
    const float* __restrict__ A, const float* __restrict__ B,
    const float* __restrict__ bias, float* __restrict__ C, int K)
{
    __shared__ uint32_t As[128][36];
    __shared__ uint32_t Bs[32][136];

    const int tid  = threadIdx.x;
    const int warp = tid >> 5, lane = tid & 31;
    const int wm = warp >> 2, wn = warp & 3;
    const int g  = lane >> 2, tg = lane & 3;
    const int m0 = blockIdx.y * 128;
    const int n0 = blockIdx.x * 128;

    const int ar  = tid >> 3;
    const int ac4 = (tid & 7) * 4;
    const int bc4 = (tid & 31) * 4;
    const int br  = tid >> 5;

    float acc[4][4][4];
    #pragma unroll
    for (int i = 0; i < 4; i++)
        #pragma unroll
        for (int j = 0; j < 4; j++)
            #pragma unroll
            for (int c = 0; c < 4; c++) acc[i][j][c] = 0.f;

    for (int kt = 0; kt < K; kt += 32) {
        __syncthreads();
        #pragma unroll
        for (int i = 0; i < 4; i++) {
            float4 v = *(const float4*)(A + (size_t)(m0 + ar + 32*i) * K + kt + ac4);
            uint4 t = {f2tf32(v.x), f2tf32(v.y), f2tf32(v.z), f2tf32(v.w)};
            *(uint4*)&As[ar + 32*i][ac4] = t;
        }
        #pragma unroll
        for (int i = 0; i < 4; i++) {
            float4 v = *(const float4*)(B + (size_t)(kt + br + 8*i) * N + n0 + bc4);
            uint4 t = {f2tf32(v.x), f2tf32(v.y), f2tf32(v.z), f2tf32(v.w)};
            *(uint4*)&Bs[br + 8*i][bc4] = t;
        }
        __syncthreads();

        #pragma unroll
        for (int ks = 0; ks < 4; ks++) {
            const int kb = ks * 8;
            uint32_t a[4][4], b[4][2];
            #pragma unroll
            for (int mt = 0; mt < 4; mt++) {
                const int mb = wm * 64 + mt * 16;
                a[mt][0] = As[mb + g    ][kb + tg    ];
                a[mt][1] = As[mb + g + 8][kb + tg    ];
                a[mt][2] = As[mb + g    ][kb + tg + 4];
                a[mt][3] = As[mb + g + 8][kb + tg + 4];
            }
            #pragma unroll
            for (int nt = 0; nt < 4; nt++) {
                const int nb = wn * 32 + nt * 8;
                b[nt][0] = Bs[kb + tg    ][nb + g];
                b[nt][1] = Bs[kb + tg + 4][nb + g];
            }
            #pragma unroll
            for (int mt = 0; mt < 4; mt++)
                #pragma unroll
                for (int nt = 0; nt < 4; nt++)
                    mma8(acc[mt][nt], a[mt][0], a[mt][1], a[mt][2], a[mt][3],
                         b[nt][0], b[nt][1]);
        }
    }

    #pragma unroll
    for (int nt = 0; nt < 4; nt++) {
        const int col = n0 + wn * 32 + nt * 8 + 2 * tg;
        float2 bv = *(const float2*)(bias + col);
        #pragma unroll
        for (int mt = 0; mt < 4; mt++) {
            const int row0 = m0 + wm * 64 + mt * 16 + g;
            float2 r0 = {acc[mt][nt][0] + bv.x, acc[mt][nt][1] + bv.y};
            float2 r1 = {acc[mt][nt][2] + bv.x, acc[mt][nt][3] + bv.y};
            *(float2*)(C + (size_t)row0 * N + col)       = r0;
            *(float2*)(C + (size_t)(row0 + 8) * N + col) = r1;
        }
    }
}

// ---------------------------------------------------------------------------
// Causal MQA flash attention on tensor cores.
// TF32 mma.m16n8k8 with 3-mma hi/lo error compensation (near-fp32 accuracy).
// BQ=64, BK=64, 256 threads (warps 2x4). Hi/lo planes for Q/K/V in smem.
// ---------------------------------------------------------------------------
#define PADQ 132   // stride == 4 mod 32: a-frag-pattern loads conflict-free
#define PADV 136   // stride == 8 mod 32: b-frag-pattern loads conflict-free
#define PADP 68

#define OFF_QHI 0
#define OFF_QLO (OFF_QHI + 64*PADQ)
#define OFF_KHI (OFF_QLO + 64*PADQ)
#define OFF_KLO (OFF_KHI + 64*PADQ)
#define OFF_VHI (OFF_KLO + 64*PADQ)
#define OFF_VLO (OFF_VHI + 64*PADV)
#define OFF_PS  (OFF_VLO + 64*PADV)
#define OFF_M   (OFF_PS  + 64*PADP)
#define ATTN_FLOATS (OFF_M + 3*64)
#define ATTN_SMEM_BYTES (ATTN_FLOATS * 4)   // 222976 B

__global__ void __launch_bounds__(256) mqa_attn_tc(
    const float* __restrict__ qkv, float* __restrict__ out)
{
    extern __shared__ float smem[];
    float (*Qhi)[PADQ] = (float(*)[PADQ])(smem + OFF_QHI);
    float (*Qlo)[PADQ] = (float(*)[PADQ])(smem + OFF_QLO);
    float (*Khi)[PADQ] = (float(*)[PADQ])(smem + OFF_KHI);
    float (*Klo)[PADQ] = (float(*)[PADQ])(smem + OFF_KLO);
    float (*Vhi)[PADV] = (float(*)[PADV])(smem + OFF_VHI);
    float (*Vlo)[PADV] = (float(*)[PADV])(smem + OFF_VLO);
    float (*Ps)[PADP]  = (float(*)[PADP])(smem + OFF_PS);
    float* m_s = smem + OFF_M;
    float* l_s = m_s + 64;
    float* f_s = l_s + 64;

    const int tid  = threadIdx.x;
    const int warp = tid >> 5, lane = tid & 31;
    const int g = lane >> 2, tg = lane & 3;
    const int wm = warp >> 2, wn = warp & 3;
    const int qt = gridDim.x - 1 - blockIdx.x;   // heavy blocks first
    const int h = blockIdx.y, b = blockIdx.z;
    const int q0 = qt * 64;

    const float* qbase = qkv + (size_t)b * SEQ * NQKV + h * HD;
    const float* kbase = qkv + (size_t)b * SEQ * NQKV + H;
    const float* vbase = kbase + HD;

    // Load + split Q tile (64 x 128) once
    for (int i = tid; i < 64 * 32; i += 256) {
        int r = i >> 5, c4 = (i & 31) * 4;
        float4 v = *(const float4*)(qbase + (size_t)(q0 + r) * NQKV + c4);
        uint32_t h0,l0,h1,l1,h2,l2,h3,l3;
        split_tf32(v.x, h0, l0); split_tf32(v.y, h1, l1);
        split_tf32(v.z, h2, l2); split_tf32(v.w, h3, l3);
        *(uint4*)&Qhi[r][c4] = make_uint4(h0, h1, h2, h3);
        *(uint4*)&Qlo[r][c4] = make_uint4(l0, l1, l2, l3);
    }
    if (tid < 64) { m_s[tid] = -1e30f; l_s[tid] = 0.f; }

    float o[2][4][4];
    #pragma unroll
    for (int mt = 0; mt < 2; mt++)
        #pragma unroll
        for (int nt = 0; nt < 4; nt++)
            #pragma unroll
            for (int c = 0; c < 4; c++) o[mt][nt][c] = 0.f;

    for (int kt = 0; kt <= qt; kt++) {
        const int k0 = kt * 64;
        __syncthreads();   // previous PV reads of Vs/Ps done
        // load + split K,V tiles (64 x 128 each)
        for (int i = tid; i < 64 * 32; i += 256) {
            int r = i >> 5, c4 = (i & 31) * 4;
            float4 kv = *(const float4*)(kbase + (size_t)(k0 + r) * NQKV + c4);
            float4 vv = *(const float4*)(vbase + (size_t)(k0 + r) * NQKV + c4);
            uint32_t h0,l0,h1,l1,h2,l2,h3,l3;
            split_tf32(kv.x, h0, l0); split_tf32(kv.y, h1, l1);
            split_tf32(kv.z, h2, l2); split_tf32(kv.w, h3, l3);
            *(uint4*)&Khi[r][c4] = make_uint4(h0, h1, h2, h3);
            *(uint4*)&Klo[r][c4] = make_uint4(l0, l1, l2, l3);
            split_tf32(vv.x, h0, l0); split_tf32(vv.y, h1, l1);
            split_tf32(vv.z, h2, l2); split_tf32(vv.w, h3, l3);
            *(uint4*)&Vhi[r][c4] = make_uint4(h0, h1, h2, h3);
            *(uint4*)&Vlo[r][c4] = make_uint4(l0, l1, l2, l3);
        }
        __syncthreads();

        // ---- S = Q @ K^T  (64x64), warp tile 32x16 ----
        float sacc[2][2][4];
        #pragma unroll
        for (int mt = 0; mt < 2; mt++)
            #pragma unroll
            for (int nt = 0; nt < 2; nt++)
                #pragma unroll
                for (int c = 0; c < 4; c++) sacc[mt][nt][c] = 0.f;

        #pragma unroll 4
        for (int ks = 0; ks < 16; ks++) {
            const int kb = ks * 8;
            uint32_t ah[2][4], al[2][4], bh[2][2], bl[2][2];
            #pragma unroll
            for (int mt = 0; mt < 2; mt++) {
                const int mb = wm * 32 + mt * 16;
                ah[mt][0] = __float_as_uint(Qhi[mb + g    ][kb + tg    ]);
                ah[mt][1] = __float_as_uint(Qhi[mb + g + 8][kb + tg    ]);
                ah[mt][2] = __float_as_uint(Qhi[mb + g    ][kb + tg + 4]);
                ah[mt][3] = __float_as_uint(Qhi[mb + g + 8][kb + tg + 4]);
                al[mt][0] = __float_as_uint(Qlo[mb + g    ][kb + tg    ]);
                al[mt][1] = __float_as_uint(Qlo[mb + g + 8][kb + tg    ]);
                al[mt][2] = __float_as_uint(Qlo[mb + g    ][kb + tg + 4]);
                al[mt][3] = __float_as_uint(Qlo[mb + g + 8][kb + tg + 4]);
            }
            #pragma unroll
            for (int nt = 0; nt < 2; nt++) {
                const int nb = wn * 16 + nt * 8;
                bh[nt][0] = __float_as_uint(Khi[nb + g][kb + tg    ]);
                bh[nt][1] = __float_as_uint(Khi[nb + g][kb + tg + 4]);
                bl[nt][0] = __float_as_uint(Klo[nb + g][kb + tg    ]);
                bl[nt][1] = __float_as_uint(Klo[nb + g][kb + tg + 4]);
            }
            #pragma unroll
            for (int mt = 0; mt < 2; mt++)
                #pragma unroll
                for (int nt = 0; nt < 2; nt++) {
                    mma8(sacc[mt][nt], ah[mt][0], ah[mt][1], ah[mt][2], ah[mt][3],
                         bh[nt][0], bh[nt][1]);
                    mma8(sacc[mt][nt], ah[mt][0], ah[mt][1], ah[mt][2], ah[mt][3],
                         bl[nt][0], bl[nt][1]);
                    mma8(sacc[mt][nt], al[mt][0], al[mt][1], al[mt][2], al[mt][3],
                         bh[nt][0], bh[nt][1]);
                }
        }

        // scale + causal mask + store S to smem
        #pragma unroll
        for (int mt = 0; mt < 2; mt++) {
            const int mb = wm * 32 + mt * 16;
            #pragma unroll
            for (int nt = 0; nt < 2; nt++) {
                const int nb = wn * 16 + nt * 8;
                const int c0 = nb + 2 * tg, c1 = c0 + 1;
                const int r0 = mb + g, r1 = mb + g + 8;
                float s00 = sacc[mt][nt][0] * SCALE;
                float s01 = sacc[mt][nt][1] * SCALE;
                float s10 = sacc[mt][nt][2] * SCALE;
                float s11 = sacc[mt][nt][3] * SCALE;
                if (k0 + c0 > q0 + r0) s00 = -1e30f;
                if (k0 + c1 > q0 + r0) s01 = -1e30f;
                if (k0 + c0 > q0 + r1) s10 = -1e30f;
                if (k0 + c1 > q0 + r1) s11 = -1e30f;
                Ps[r0][c0] = s00;  Ps[r0][c1] = s01;
                Ps[r1][c0] = s10;  Ps[r1][c1] = s11;
            }
        }
        __syncthreads();

        // ---- online softmax: 4 threads per row ----
        {
            const int row = tid >> 2, sub = tid & 3;
            float v[16];
            float mold = m_s[row];
            float mx = mold;
            #pragma unroll
            for (int c = 0; c < 16; c++) {
                v[c] = Ps[row][sub * 16 + c];
                mx = fmaxf(mx, v[c]);
            }
            mx = fmaxf(mx, __shfl_xor_sync(0xffffffffu, mx, 1));
            mx = fmaxf(mx, __shfl_xor_sync(0xffffffffu, mx, 2));
            float sum = 0.f;
            #pragma unroll
            for (int c = 0; c < 16; c++) {
                float p = fast_exp(v[c] - mx);
                Ps[row][sub * 16 + c] = p;
                sum += p;
            }
            sum += __shfl_xor_sync(0xffffffffu, sum, 1);
            sum += __shfl_xor_sync(0xffffffffu, sum, 2);
            if (sub == 0) {
                float f = fast_exp(mold - mx);
                l_s[row] = l_s[row] * f + sum;
                m_s[row] = mx;
                f_s[row] = f;
            }
        }
        __syncthreads();

        // ---- O = O*f + P @ V  (64x128), warp tile 32x32 ----
        float fr[2][2];
        #pragma unroll
        for (int mt = 0; mt < 2; mt++) {
            const int mb = wm * 32 + mt * 16;
            fr[mt][0] = f_s[mb + g];
            fr[mt][1] = f_s[mb + g + 8];
        }
        #pragma unroll
        for (int mt = 0; mt < 2; mt++)
            #pragma unroll
            for (int nt = 0; nt < 4; nt++) {
                o[mt][nt][0] *= fr[mt][0];  o[mt][nt][1] *= fr[mt][0];
                o[mt][nt][2] *= fr[mt][1];  o[mt][nt][3] *= fr[mt][1];
            }

        #pragma unroll 4
        for (int ks = 0; ks < 8; ks++) {
            const int kb = ks * 8;
            uint32_t ah[2][4], al[2][4];
            #pragma unroll
            for (int mt = 0; mt < 2; mt++) {
                const int mb = wm * 32 + mt * 16;
                split_tf32(Ps[mb + g    ][kb + tg    ], ah[mt][0], al[mt][0]);
                split_tf32(Ps[mb + g + 8][kb + tg    ], ah[mt][1], al[mt][1]);
                split_tf32(Ps[mb + g    ][kb + tg + 4], ah[mt][2], al[mt][2]);
                split_tf32(Ps[mb + g + 8][kb + tg + 4], ah[mt][3], al[mt][3]);
            }
            #pragma unroll
            for (int nt = 0; nt < 4; nt++) {
                const int nb = wn * 32 + nt * 8;
                uint32_t bh0 = __float_as_uint(Vhi[kb + tg    ][nb + g]);
                uint32_t bh1 = __float_as_uint(Vhi[kb + tg + 4][nb + g]);
                uint32_t bl0 = __float_as_uint(Vlo[kb + tg    ][nb + g]);
                uint32_t bl1 = __float_as_uint(Vlo[kb + tg + 4][nb + g]);
                #pragma unroll
                for (int mt = 0; mt < 2; mt++) {
                    mma8(o[mt][nt], ah[mt][0], ah[mt][1], ah[mt][2], ah[mt][3], bh0, bh1);
                    mma8(o[mt][nt], ah[mt][0], ah[mt][1], ah[mt][2], ah[mt][3], bl0, bl1);
                    mma8(o[mt][nt], al[mt][0], al[mt][1], al[mt][2], al[mt][3], bh0, bh1);
                }
            }
        }
    }

    __syncthreads();
    // final write: o / l
    #pragma unroll
    for (int mt = 0; mt < 2; mt++) {
        const int mb = wm * 32 + mt * 16;
        const float inv0 = 1.f / l_s[mb + g];
        const float inv1 = 1.f / l_s[mb + g + 8];
        #pragma unroll
        for (int nt = 0; nt < 4; nt++) {
            const int col = wn * 32 + nt * 8 + 2 * tg;
            size_t row0 = (size_t)(b * SEQ + q0 + mb + g) * H + h * HD + col;
            size_t row1 = (size_t)(b * SEQ + q0 + mb + g + 8) * H + h * HD + col;
            float2 r0 = {o[mt][nt][0] * inv0, o[mt][nt][1] * inv0};
            float2 r1 = {o[mt][nt][2] * inv1, o[mt][nt][3] * inv1};
            *(float2*)(out + row0) = r0;
            *(float2*)(out + row1) = r1;
        }
    }
}

// ---------------------------------------------------------------------------

extern "C" void kernel_launch(void* const* d_in, const int* in_sizes, int n_in,
                              void* d_out, int out_size)
{
    (void)in_sizes; (void)n_in; (void)out_size;
    const float* x     = (const float*)d_in[0];
    const float* Wqkv  = (const float*)d_in[1];
    const float* bqkv  = (const float*)d_in[2];
    const float* Wproj = (const float*)d_in[3];
    const float* bproj = (const float*)d_in[4];
    float* out = (float*)d_out;

    float *qkv_ptr, *attn_ptr;
    cudaGetSymbolAddress((void**)&qkv_ptr, g_qkv);
    cudaGetSymbolAddress((void**)&attn_ptr, g_attn);

    cudaFuncSetAttribute(mqa_attn_tc, cudaFuncAttributeMaxDynamicSharedMemorySize,
                         ATTN_SMEM_BYTES);

    // 1) QKV GEMM (TF32 tensor cores)
    gemm_tf32<NQKV><<<dim3(NQKV / 128, (BATCH * SEQ) / 128), 256>>>(
        x, Wqkv, bqkv, qkv_ptr, H);

    // 2) causal MQA flash attention (TF32 tensor cores, 3-mma compensated)
    mqa_attn_tc<<<dim3(SEQ / 64, NH, BATCH), 256, ATTN_SMEM_BYTES>>>(qkv_ptr, attn_ptr);

    // 3) proj GEMM (TF32 tensor cores)
    gemm_tf32<H><<<dim3(H / 128, (BATCH * SEQ) / 128), 256>>>(
        attn_ptr, Wproj, bproj, out, H);
}

// round 4
// speedup vs baseline: 2.3277x; 1.0804x over previous
#include <cuda_runtime.h>
#include <math.h>
#include <stdint.h>

#define H 2048
#define NH 16
#define HD 128
#define SEQ 2048
#define BATCH 2
#define NQKV (H + 2*HD)   // 2304
#define SCALE 0.08838834764831843f  // 1/sqrt(128)

// Scratch (allocation-free rule: __device__ globals)
__device__ float g_qkv[(size_t)BATCH * SEQ * NQKV];   // ~37.7 MB
__device__ float g_attn[(size_t)BATCH * SEQ * H];     // ~33.5 MB

__device__ __forceinline__ uint32_t f2tf32(float x) {
    uint32_t r;
    asm("cvt.rna.tf32.f32 %0, %1;" : "=r"(r) : "f"(x));
    return r;
}
__device__ __forceinline__ void mma8(float* c, uint32_t a0, uint32_t a1,
                                     uint32_t a2, uint32_t a3,
                                     uint32_t b0, uint32_t b1) {
    asm volatile(
        "mma.sync.aligned.m16n8k8.row.col.f32.tf32.tf32.f32 "
        "{%0,%1,%2,%3}, {%4,%5,%6,%7}, {%8,%9}, {%0,%1,%2,%3};"
        : "+f"(c[0]), "+f"(c[1]), "+f"(c[2]), "+f"(c[3])
        : "r"(a0), "r"(a1), "r"(a2), "r"(a3), "r"(b0), "r"(b1));
}
__device__ __forceinline__ void mma16bf(float* c, const uint32_t* a,
                                        uint32_t b0, uint32_t b1) {
    asm volatile(
        "mma.sync.aligned.m16n8k16.row.col.f32.bf16.bf16.f32 "
        "{%0,%1,%2,%3}, {%4,%5,%6,%7}, {%8,%9}, {%0,%1,%2,%3};"
        : "+f"(c[0]), "+f"(c[1]), "+f"(c[2]), "+f"(c[3])
        : "r"(a[0]), "r"(a[1]), "r"(a[2]), "r"(a[3]), "r"(b0), "r"(b1));
}
__device__ __forceinline__ uint32_t prmt(uint32_t a, uint32_t b, uint32_t s) {
    uint32_t d;
    asm("prmt.b32 %0, %1, %2, %3;" : "=r"(d) : "r"(a), "r"(b), "r"(s));
    return d;
}
// bf16 hi/lo split: x ~= hi + lo with ~16 mantissa bits combined.
__device__ __forceinline__ void split_bf16(float x, uint32_t& hi, uint32_t& lo) {
    uint16_t h, l;
    asm("cvt.rn.bf16.f32 %0, %1;" : "=h"(h) : "f"(x));
    float r = x - __uint_as_float((uint32_t)h << 16);
    asm("cvt.rn.bf16.f32 %0, %1;" : "=h"(l) : "f"(r));
    hi = h; lo = l;
}

// Fast exp on the FMA pipe (avoids the MUFU throughput floor).
// Valid for x <= 0. ~1e-7 rel err.
__device__ __forceinline__ float fast_exp(float x) {
    float t = fmaxf(x * 1.4426950408889634f, -126.0f);
    float fl = floorf(t);
    float f = t - fl;
    float p =              1.535336188319500e-4f;
    p = fmaf(p, f, 1.339887440266574e-3f);
    p = fmaf(p, f, 9.618437357674640e-3f);
    p = fmaf(p, f, 5.550332471162809e-2f);
    p = fmaf(p, f, 2.402264791363012e-1f);
    p = fmaf(p, f, 6.931472028550421e-1f);
    p = fmaf(p, f, 1.0f);
    uint32_t sc = ((uint32_t)(int)(fl + 127.0f)) << 23;
    return p * __uint_as_float(sc);
}

// ---------------------------------------------------------------------------
// TF32 tensor-core GEMM with bias + register prefetch software pipeline.
// BM=128, BN=128, BK=32, 256 threads, m16n8k8 tf32.
// ---------------------------------------------------------------------------
template<int N>
__global__ void __launch_bounds__(256) gemm_tf32(
    const float* __restrict__ A, const float* __restrict__ B,
    const float* __restrict__ bias, float* __restrict__ C, int K)
{
    __shared__ uint32_t As[128][36];
    __shared__ uint32_t Bs[32][136];

    const int tid  = threadIdx.x;
    const int warp = tid >> 5, lane = tid & 31;
    const int wm = warp >> 2, wn = warp & 3;
    const int g  = lane >> 2, tg = lane & 3;
    const int m0 = blockIdx.y * 128;
    const int n0 = blockIdx.x * 128;

    const int ar  = tid >> 3;
    const int ac4 = (tid & 7) * 4;
    const int bc4 = (tid & 31) * 4;
    const int br  = tid >> 5;

    float acc[4][4][4];
    #pragma unroll
    for (int i = 0; i < 4; i++)
        #pragma unroll
        for (int j = 0; j < 4; j++)
            #pragma unroll
            for (int c = 0; c < 4; c++) acc[i][j][c] = 0.f;

    // prefetch tile 0
    float4 pa[4], pb[4];
    #pragma unroll
    for (int i = 0; i < 4; i++) {
        pa[i] = *(const float4*)(A + (size_t)(m0 + ar + 32*i) * K + ac4);
        pb[i] = *(const float4*)(B + (size_t)(br + 8*i) * N + n0 + bc4);
    }

    for (int kt = 0; kt < K; kt += 32) {
        __syncthreads();
        #pragma unroll
        for (int i = 0; i < 4; i++) {
            uint4 ta = {f2tf32(pa[i].x), f2tf32(pa[i].y), f2tf32(pa[i].z), f2tf32(pa[i].w)};
            *(uint4*)&As[ar + 32*i][ac4] = ta;
            uint4 tb = {f2tf32(pb[i].x), f2tf32(pb[i].y), f2tf32(pb[i].z), f2tf32(pb[i].w)};
            *(uint4*)&Bs[br + 8*i][bc4] = tb;
        }
        __syncthreads();

        if (kt + 32 < K) {
            #pragma unroll
            for (int i = 0; i < 4; i++) {
                pa[i] = *(const float4*)(A + (size_t)(m0 + ar + 32*i) * K + kt + 32 + ac4);
                pb[i] = *(const float4*)(B + (size_t)(kt + 32 + br + 8*i) * N + n0 + bc4);
            }
        }

        #pragma unroll
        for (int ks = 0; ks < 4; ks++) {
            const int kb = ks * 8;
            uint32_t a[4][4], b[4][2];
            #pragma unroll
            for (int mt = 0; mt < 4; mt++) {
                const int mb = wm * 64 + mt * 16;
                a[mt][0] = As[mb + g    ][kb + tg    ];
                a[mt][1] = As[mb + g + 8][kb + tg    ];
                a[mt][2] = As[mb + g    ][kb + tg + 4];
                a[mt][3] = As[mb + g + 8][kb + tg + 4];
            }
            #pragma unroll
            for (int nt = 0; nt < 4; nt++) {
                const int nb = wn * 32 + nt * 8;
                b[nt][0] = Bs[kb + tg    ][nb + g];
                b[nt][1] = Bs[kb + tg + 4][nb + g];
            }
            #pragma unroll
            for (int mt = 0; mt < 4; mt++)
                #pragma unroll
                for (int nt = 0; nt < 4; nt++)
                    mma8(acc[mt][nt], a[mt][0], a[mt][1], a[mt][2], a[mt][3],
                         b[nt][0], b[nt][1]);
        }
    }

    #pragma unroll
    for (int nt = 0; nt < 4; nt++) {
        const int col = n0 + wn * 32 + nt * 8 + 2 * tg;
        float2 bv = *(const float2*)(bias + col);
        #pragma unroll
        for (int mt = 0; mt < 4; mt++) {
            const int row0 = m0 + wm * 64 + mt * 16 + g;
            float2 r0 = {acc[mt][nt][0] + bv.x, acc[mt][nt][1] + bv.y};
            float2 r1 = {acc[mt][nt][2] + bv.x, acc[mt][nt][3] + bv.y};
            *(float2*)(C + (size_t)row0 * N + col)       = r0;
            *(float2*)(C + (size_t)(row0 + 8) * N + col) = r1;
        }
    }
}

// ---------------------------------------------------------------------------
// Causal MQA flash attention: bf16 m16n8k16 mma with 3-mma hi/lo compensation.
// BQ=64, BK=64, 256 threads (warps 2x4).
// Smem (u32 units, strides == 4 mod 32 -> conflict-free fragment loads):
//   Qhi2/Qlo2 [64][68]  half2 pairs along head-dim
//   Khi2/Klo2 [64][68]  half2 pairs along head-dim
//   Vp        [64][132] packed {hi,lo} per element (prmt-extracted b-frags)
//   Sf        [64][68]  float scores
//   Phi2/Plo2 [64][36]  half2 pairs along k-pos (split once in softmax)
// ---------------------------------------------------------------------------
#define PQ2 68
#define PVP 132
#define PSF 68
#define PP2 36

#define OFF_QHI 0
#define OFF_QLO (OFF_QHI + 64*PQ2)
#define OFF_KHI (OFF_QLO + 64*PQ2)
#define OFF_KLO (OFF_KHI + 64*PQ2)
#define OFF_VP  (OFF_KLO + 64*PQ2)
#define OFF_SF  (OFF_VP  + 64*PVP)
#define OFF_PHI (OFF_SF  + 64*PSF)
#define OFF_PLO (OFF_PHI + 64*PP2)
#define OFF_M   (OFF_PLO + 64*PP2)
#define ATTN_U32 (OFF_M + 3*64)
#define ATTN_SMEM_BYTES (ATTN_U32 * 4)

__global__ void __launch_bounds__(256) mqa_attn_tc(
    const float* __restrict__ qkv, float* __restrict__ out)
{
    extern __shared__ uint32_t smem_u[];
    uint32_t* Qhi2 = smem_u + OFF_QHI;
    uint32_t* Qlo2 = smem_u + OFF_QLO;
    uint32_t* Khi2 = smem_u + OFF_KHI;
    uint32_t* Klo2 = smem_u + OFF_KLO;
    uint32_t* Vp   = smem_u + OFF_VP;
    float*    Sf   = (float*)(smem_u + OFF_SF);
    uint32_t* Phi2 = smem_u + OFF_PHI;
    uint32_t* Plo2 = smem_u + OFF_PLO;
    float* m_s = (float*)(smem_u + OFF_M);
    float* l_s = m_s + 64;
    float* f_s = l_s + 64;

    const int tid  = threadIdx.x;
    const int warp = tid >> 5, lane = tid & 31;
    const int g = lane >> 2, tg = lane & 3;
    const int wm = warp >> 2, wn = warp & 3;
    const int qt = gridDim.x - 1 - blockIdx.x;   // heavy blocks first
    const int h = blockIdx.y, b = blockIdx.z;
    const int q0 = qt * 64;

    const float* qbase = qkv + (size_t)b * SEQ * NQKV + h * HD;
    const float* kbase = qkv + (size_t)b * SEQ * NQKV + H;
    const float* vbase = kbase + HD;

    // Load + split Q tile (64 x 128) once
    for (int i = tid; i < 64 * 32; i += 256) {
        int r = i >> 5, c4 = (i & 31) * 4, c2 = (i & 31) * 2;
        float4 v = *(const float4*)(qbase + (size_t)(q0 + r) * NQKV + c4);
        uint32_t h0,l0,h1,l1,h2,l2,h3,l3;
        split_bf16(v.x, h0, l0); split_bf16(v.y, h1, l1);
        split_bf16(v.z, h2, l2); split_bf16(v.w, h3, l3);
        Qhi2[r*PQ2 + c2]     = h0 | (h1 << 16);
        Qhi2[r*PQ2 + c2 + 1] = h2 | (h3 << 16);
        Qlo2[r*PQ2 + c2]     = l0 | (l1 << 16);
        Qlo2[r*PQ2 + c2 + 1] = l2 | (l3 << 16);
    }
    if (tid < 64) { m_s[tid] = -1e30f; l_s[tid] = 0.f; }

    float o[2][4][4];
    #pragma unroll
    for (int mt = 0; mt < 2; mt++)
        #pragma unroll
        for (int nt = 0; nt < 4; nt++)
            #pragma unroll
            for (int c = 0; c < 4; c++) o[mt][nt][c] = 0.f;

    for (int kt = 0; kt <= qt; kt++) {
        const int k0 = kt * 64;
        __syncthreads();   // prior-iteration readers of K/V done
        // load + split K (hd-paired planes) and V (packed word) tiles
        for (int i = tid; i < 64 * 32; i += 256) {
            int r = i >> 5, c4 = (i & 31) * 4, c2 = (i & 31) * 2;
            float4 kv = *(const float4*)(kbase + (size_t)(k0 + r) * NQKV + c4);
            float4 vv = *(const float4*)(vbase + (size_t)(k0 + r) * NQKV + c4);
            uint32_t h0,l0,h1,l1,h2,l2,h3,l3;
            split_bf16(kv.x, h0, l0); split_bf16(kv.y, h1, l1);
            split_bf16(kv.z, h2, l2); split_bf16(kv.w, h3, l3);
            Khi2[r*PQ2 + c2]     = h0 | (h1 << 16);
            Khi2[r*PQ2 + c2 + 1] = h2 | (h3 << 16);
            Klo2[r*PQ2 + c2]     = l0 | (l1 << 16);
            Klo2[r*PQ2 + c2 + 1] = l2 | (l3 << 16);
            split_bf16(vv.x, h0, l0); split_bf16(vv.y, h1, l1);
            split_bf16(vv.z, h2, l2); split_bf16(vv.w, h3, l3);
            Vp[r*PVP + c4    ] = l0 | (h0 << 16);
            Vp[r*PVP + c4 + 1] = l1 | (h1 << 16);
            Vp[r*PVP + c4 + 2] = l2 | (h2 << 16);
            Vp[r*PVP + c4 + 3] = l3 | (h3 << 16);
        }
        __syncthreads();

        // ---- S = Q @ K^T  (64x64), warp tile 32x16, 8 k-steps of 16 ----
        float sacc[2][2][4];
        #pragma unroll
        for (int mt = 0; mt < 2; mt++)
            #pragma unroll
            for (int nt = 0; nt < 2; nt++)
                #pragma unroll
                for (int c = 0; c < 4; c++) sacc[mt][nt][c] = 0.f;

        #pragma unroll
        for (int ks = 0; ks < 8; ks++) {
            const int kb2 = ks * 8;
            uint32_t ah[2][4], al[2][4], bh[2][2], bl[2][2];
            #pragma unroll
            for (int mt = 0; mt < 2; mt++) {
                const int mb = wm * 32 + mt * 16;
                ah[mt][0] = Qhi2[(mb + g    )*PQ2 + kb2 + tg    ];
                ah[mt][1] = Qhi2[(mb + g + 8)*PQ2 + kb2 + tg    ];
                ah[mt][2] = Qhi2[(mb + g    )*PQ2 + kb2 + tg + 4];
                ah[mt][3] = Qhi2[(mb + g + 8)*PQ2 + kb2 + tg + 4];
                al[mt][0] = Qlo2[(mb + g    )*PQ2 + kb2 + tg    ];
                al[mt][1] = Qlo2[(mb + g + 8)*PQ2 + kb2 + tg    ];
                al[mt][2] = Qlo2[(mb + g    )*PQ2 + kb2 + tg + 4];
                al[mt][3] = Qlo2[(mb + g + 8)*PQ2 + kb2 + tg + 4];
            }
            #pragma unroll
            for (int nt = 0; nt < 2; nt++) {
                const int nb = wn * 16 + nt * 8;
                bh[nt][0] = Khi2[(nb + g)*PQ2 + kb2 + tg    ];
                bh[nt][1] = Khi2[(nb + g)*PQ2 + kb2 + tg + 4];
                bl[nt][0] = Klo2[(nb + g)*PQ2 + kb2 + tg    ];
                bl[nt][1] = Klo2[(nb + g)*PQ2 + kb2 + tg + 4];
            }
            #pragma unroll
            for (int mt = 0; mt < 2; mt++)
                #pragma unroll
                for (int nt = 0; nt < 2; nt++) {
                    mma16bf(sacc[mt][nt], ah[mt], bh[nt][0], bh[nt][1]);
                    mma16bf(sacc[mt][nt], ah[mt], bl[nt][0], bl[nt][1]);
                    mma16bf(sacc[mt][nt], al[mt], bh[nt][0], bh[nt][1]);
                }
        }

        // scale + causal mask + store S
        #pragma unroll
        for (int mt = 0; mt < 2; mt++) {
            const int mb = wm * 32 + mt * 16;
            #pragma unroll
            for (int nt = 0; nt < 2; nt++) {
                const int nb = wn * 16 + nt * 8;
                const int c0 = nb + 2 * tg, c1 = c0 + 1;
                const int r0 = mb + g, r1 = mb + g + 8;
                float s00 = sacc[mt][nt][0] * SCALE;
                float s01 = sacc[mt][nt][1] * SCALE;
                float s10 = sacc[mt][nt][2] * SCALE;
                float s11 = sacc[mt][nt][3] * SCALE;
                if (k0 + c0 > q0 + r0) s00 = -1e30f;
                if (k0 + c1 > q0 + r0) s01 = -1e30f;
                if (k0 + c0 > q0 + r1) s10 = -1e30f;
                if (k0 + c1 > q0 + r1) s11 = -1e30f;
                Sf[r0*PSF + c0] = s00;  Sf[r0*PSF + c1] = s01;
                Sf[r1*PSF + c0] = s10;  Sf[r1*PSF + c1] = s11;
            }
        }
        __syncthreads();

        // ---- online softmax: 4 threads per row; writes bf16 P planes ----
        {
            const int row = tid >> 2, sub = tid & 3;
            float v[16];
            float mold = m_s[row];
            float mx = mold;
            #pragma unroll
            for (int c = 0; c < 16; c++) {
                v[c] = Sf[row*PSF + sub * 16 + c];
                mx = fmaxf(mx, v[c]);
            }
            mx = fmaxf(mx, __shfl_xor_sync(0xffffffffu, mx, 1));
            mx = fmaxf(mx, __shfl_xor_sync(0xffffffffu, mx, 2));
            float sum = 0.f;
            #pragma unroll
            for (int c = 0; c < 8; c++) {
                float p0 = fast_exp(v[2*c]     - mx);
                float p1 = fast_exp(v[2*c + 1] - mx);
                sum += p0 + p1;
                uint32_t h0, l0, h1, l1;
                split_bf16(p0, h0, l0);
                split_bf16(p1, h1, l1);
                Phi2[row*PP2 + sub * 8 + c] = h0 | (h1 << 16);
                Plo2[row*PP2 + sub * 8 + c] = l0 | (l1 << 16);
            }
            sum += __shfl_xor_sync(0xffffffffu, sum, 1);
            sum += __shfl_xor_sync(0xffffffffu, sum, 2);
            if (sub == 0) {
                float f = fast_exp(mold - mx);
                l_s[row] = l_s[row] * f + sum;
                m_s[row] = mx;
                f_s[row] = f;
            }
        }
        __syncthreads();

        // ---- O = O*f + P @ V  (64x128), warp tile 32x32, 4 k-steps ----
        float fr[2][2];
        #pragma unroll
        for (int mt = 0; mt < 2; mt++) {
            const int mb = wm * 32 + mt * 16;
            fr[mt][0] = f_s[mb + g];
            fr[mt][1] = f_s[mb + g + 8];
        }
        #pragma unroll
        for (int mt = 0; mt < 2; mt++)
            #pragma unroll
            for (int nt = 0; nt < 4; nt++) {
                o[mt][nt][0] *= fr[mt][0];  o[mt][nt][1] *= fr[mt][0];
                o[mt][nt][2] *= fr[mt][1];  o[mt][nt][3] *= fr[mt][1];
            }

        #pragma unroll
        for (int ks = 0; ks < 4; ks++) {
            const int kb2 = ks * 8;       // half2 col base in P planes
            const int kb  = ks * 16;      // k-pos base in V
            uint32_t ah[2][4], al[2][4];
            #pragma unroll
            for (int mt = 0; mt < 2; mt++) {
                const int mb = wm * 32 + mt * 16;
                ah[mt][0] = Phi2[(mb + g    )*PP2 + kb2 + tg    ];
                ah[mt][1] = Phi2[(mb + g + 8)*PP2 + kb2 + tg    ];
                ah[mt][2] = Phi2[(mb + g    )*PP2 + kb2 + tg + 4];
                ah[mt][3] = Phi2[(mb + g + 8)*PP2 + kb2 + tg + 4];
                al[mt][0] = Plo2[(mb + g    )*PP2 + kb2 + tg    ];
                al[mt][1] = Plo2[(mb + g + 8)*PP2 + kb2 + tg    ];
                al[mt][2] = Plo2[(mb + g    )*PP2 + kb2 + tg + 4];
                al[mt][3] = Plo2[(mb + g + 8)*PP2 + kb2 + tg + 4];
            }
            #pragma unroll
            for (int nt = 0; nt < 4; nt++) {
                const int nb = wn * 32 + nt * 8;
                uint32_t w00 = Vp[(kb + 2*tg    )*PVP + nb + g];
                uint32_t w01 = Vp[(kb + 2*tg + 1)*PVP + nb + g];
                uint32_t w10 = Vp[(kb + 2*tg + 8)*PVP + nb + g];
                uint32_t w11 = Vp[(kb + 2*tg + 9)*PVP + nb + g];
                uint32_t bh0 = prmt(w00, w01, 0x7632u);
                uint32_t bl0 = prmt(w00, w01, 0x5410u);
                uint32_t bh1 = prmt(w10, w11, 0x7632u);
                uint32_t bl1 = prmt(w10, w11, 0x5410u);
                #pragma unroll
                for (int mt = 0; mt < 2; mt++) {
                    mma16bf(o[mt][nt], ah[mt], bh0, bh1);
                    mma16bf(o[mt][nt], ah[mt], bl0, bl1);
                    mma16bf(o[mt][nt], al[mt], bh0, bh1);
                }
            }
        }
    }

    __syncthreads();
    // final write: o / l
    #pragma unroll
    for (int mt = 0; mt < 2; mt++) {
        const int mb = wm * 32 + mt * 16;
        const float inv0 = 1.f / l_s[mb + g];
        const float inv1 = 1.f / l_s[mb + g + 8];
        #pragma unroll
        for (int nt = 0; nt < 4; nt++) {
            const int col = wn * 32 + nt * 8 + 2 * tg;
            size_t row0 = (size_t)(b * SEQ + q0 + mb + g) * H + h * HD + col;
            size_t row1 = (size_t)(b * SEQ + q0 + mb + g + 8) * H + h * HD + col;
            float2 r0 = {o[mt][nt][0] * inv0, o[mt][nt][1] * inv0};
            float2 r1 = {o[mt][nt][2] * inv1, o[mt][nt][3] * inv1};
            *(float2*)(out + row0) = r0;
            *(float2*)(out + row1) = r1;
        }
    }
}

// ---------------------------------------------------------------------------

extern "C" void kernel_launch(void* const* d_in, const int* in_sizes, int n_in,
                              void* d_out, int out_size)
{
    (void)in_sizes; (void)n_in; (void)out_size;
    const float* x     = (const float*)d_in[0];
    const float* Wqkv  = (const float*)d_in[1];
    const float* bqkv  = (const float*)d_in[2];
    const float* Wproj = (const float*)d_in[3];
    const float* bproj = (const float*)d_in[4];
    float* out = (float*)d_out;

    float *qkv_ptr, *attn_ptr;
    cudaGetSymbolAddress((void**)&qkv_ptr, g_qkv);
    cudaGetSymbolAddress((void**)&attn_ptr, g_attn);

    cudaFuncSetAttribute(mqa_attn_tc, cudaFuncAttributeMaxDynamicSharedMemorySize,
                         ATTN_SMEM_BYTES);

    // 1) QKV GEMM (TF32 tensor cores, reg prefetch)
    gemm_tf32<NQKV><<<dim3(NQKV / 128, (BATCH * SEQ) / 128), 256>>>(
        x, Wqkv, bqkv, qkv_ptr, H);

    // 2) causal MQA flash attention (bf16 mma, 3-mma compensated)
    mqa_attn_tc<<<dim3(SEQ / 64, NH, BATCH), 256, ATTN_SMEM_BYTES>>>(qkv_ptr, attn_ptr);

    // 3) proj GEMM (TF32 tensor cores, reg prefetch)
    gemm_tf32<H><<<dim3(H / 128, (BATCH * SEQ) / 128), 256>>>(
        attn_ptr, Wproj, bproj, out, H);
}

// round 5
// speedup vs baseline: 2.5495x; 1.0953x over previous
#include <cuda_runtime.h>
#include <math.h>
#include <stdint.h>

#define H 2048
#define NH 16
#define HD 128
#define SEQ 2048
#define BATCH 2
#define NQKV (H + 2*HD)   // 2304
#define SCALE 0.08838834764831843f  // 1/sqrt(128)

// Scratch (allocation-free rule: __device__ globals)
__device__ float g_qkv[(size_t)BATCH * SEQ * NQKV];   // ~37.7 MB
__device__ float g_attn[(size_t)BATCH * SEQ * H];     // ~33.5 MB

__device__ __forceinline__ uint32_t f2tf32(float x) {
    uint32_t r;
    asm("cvt.rna.tf32.f32 %0, %1;" : "=r"(r) : "f"(x));
    return r;
}
__device__ __forceinline__ void mma8(float* c, uint32_t a0, uint32_t a1,
                                     uint32_t a2, uint32_t a3,
                                     uint32_t b0, uint32_t b1) {
    asm volatile(
        "mma.sync.aligned.m16n8k8.row.col.f32.tf32.tf32.f32 "
        "{%0,%1,%2,%3}, {%4,%5,%6,%7}, {%8,%9}, {%0,%1,%2,%3};"
        : "+f"(c[0]), "+f"(c[1]), "+f"(c[2]), "+f"(c[3])
        : "r"(a0), "r"(a1), "r"(a2), "r"(a3), "r"(b0), "r"(b1));
}
__device__ __forceinline__ void mma16bf(float* c, const uint32_t* a,
                                        uint32_t b0, uint32_t b1) {
    asm volatile(
        "mma.sync.aligned.m16n8k16.row.col.f32.bf16.bf16.f32 "
        "{%0,%1,%2,%3}, {%4,%5,%6,%7}, {%8,%9}, {%0,%1,%2,%3};"
        : "+f"(c[0]), "+f"(c[1]), "+f"(c[2]), "+f"(c[3])
        : "r"(a[0]), "r"(a[1]), "r"(a[2]), "r"(a[3]), "r"(b0), "r"(b1));
}
__device__ __forceinline__ void ldsm4(uint32_t* r, uint32_t addr) {
    asm volatile("ldmatrix.sync.aligned.m8n8.x4.shared.b16 {%0,%1,%2,%3}, [%4];"
        : "=r"(r[0]), "=r"(r[1]), "=r"(r[2]), "=r"(r[3]) : "r"(addr));
}
__device__ __forceinline__ uint32_t prmt(uint32_t a, uint32_t b, uint32_t s) {
    uint32_t d;
    asm("prmt.b32 %0, %1, %2, %3;" : "=r"(d) : "r"(a), "r"(b), "r"(s));
    return d;
}
__device__ __forceinline__ uint32_t sm_addr(const void* p) {
    return (uint32_t)__cvta_generic_to_shared(p);
}
// bf16 hi/lo split: x ~= hi + lo with ~16 mantissa bits combined.
__device__ __forceinline__ void split_bf16(float x, uint32_t& hi, uint32_t& lo) {
    uint16_t h, l;
    asm("cvt.rn.bf16.f32 %0, %1;" : "=h"(h) : "f"(x));
    float r = x - __uint_as_float((uint32_t)h << 16);
    asm("cvt.rn.bf16.f32 %0, %1;" : "=h"(l) : "f"(r));
    hi = h; lo = l;
}

// Fast exp on the FMA pipe (avoids the MUFU throughput floor). x <= 0.
__device__ __forceinline__ float fast_exp(float x) {
    float t = fmaxf(x * 1.4426950408889634f, -126.0f);
    float fl = floorf(t);
    float f = t - fl;
    float p =              1.535336188319500e-4f;
    p = fmaf(p, f, 1.339887440266574e-3f);
    p = fmaf(p, f, 9.618437357674640e-3f);
    p = fmaf(p, f, 5.550332471162809e-2f);
    p = fmaf(p, f, 2.402264791363012e-1f);
    p = fmaf(p, f, 6.931472028550421e-1f);
    p = fmaf(p, f, 1.0f);
    uint32_t sc = ((uint32_t)(int)(fl + 127.0f)) << 23;
    return p * __uint_as_float(sc);
}

// ---------------------------------------------------------------------------
// TF32 tensor-core GEMM with bias (round-3 version: no prefetch).
// ---------------------------------------------------------------------------
template<int N>
__global__ void __launch_bounds__(256) gemm_tf32(
    const float* __restrict__ A, const float* __restrict__ B,
    const float* __restrict__ bias, float* __restrict__ C, int K)
{
    __shared__ uint32_t As[128][36];
    __shared__ uint32_t Bs[32][136];

    const int tid  = threadIdx.x;
    const int warp = tid >> 5, lane = tid & 31;
    const int wm = warp >> 2, wn = warp & 3;
    const int g  = lane >> 2, tg = lane & 3;
    const int m0 = blockIdx.y * 128;
    const int n0 = blockIdx.x * 128;

    const int ar  = tid >> 3;
    const int ac4 = (tid & 7) * 4;
    const int bc4 = (tid & 31) * 4;
    const int br  = tid >> 5;

    float acc[4][4][4];
    #pragma unroll
    for (int i = 0; i < 4; i++)
        #pragma unroll
        for (int j = 0; j < 4; j++)
            #pragma unroll
            for (int c = 0; c < 4; c++) acc[i][j][c] = 0.f;

    for (int kt = 0; kt < K; kt += 32) {
        __syncthreads();
        #pragma unroll
        for (int i = 0; i < 4; i++) {
            float4 v = *(const float4*)(A + (size_t)(m0 + ar + 32*i) * K + kt + ac4);
            uint4 t = {f2tf32(v.x), f2tf32(v.y), f2tf32(v.z), f2tf32(v.w)};
            *(uint4*)&As[ar + 32*i][ac4] = t;
        }
        #pragma unroll
        for (int i = 0; i < 4; i++) {
            float4 v = *(const float4*)(B + (size_t)(kt + br + 8*i) * N + n0 + bc4);
            uint4 t = {f2tf32(v.x), f2tf32(v.y), f2tf32(v.z), f2tf32(v.w)};
            *(uint4*)&Bs[br + 8*i][bc4] = t;
        }
        __syncthreads();

        #pragma unroll
        for (int ks = 0; ks < 4; ks++) {
            const int kb = ks * 8;
            uint32_t a[4][4], b[4][2];
            #pragma unroll
            for (int mt = 0; mt < 4; mt++) {
                const int mb = wm * 64 + mt * 16;
                a[mt][0] = As[mb + g    ][kb + tg    ];
                a[mt][1] = As[mb + g + 8][kb + tg    ];
                a[mt][2] = As[mb + g    ][kb + tg + 4];
                a[mt][3] = As[mb + g + 8][kb + tg + 4];
            }
            #pragma unroll
            for (int nt = 0; nt < 4; nt++) {
                const int nb = wn * 32 + nt * 8;
                b[nt][0] = Bs[kb + tg    ][nb + g];
                b[nt][1] = Bs[kb + tg + 4][nb + g];
            }
            #pragma unroll
            for (int mt = 0; mt < 4; mt++)
                #pragma unroll
                for (int nt = 0; nt < 4; nt++)
                    mma8(acc[mt][nt], a[mt][0], a[mt][1], a[mt][2], a[mt][3],
                         b[nt][0], b[nt][1]);
        }
    }

    #pragma unroll
    for (int nt = 0; nt < 4; nt++) {
        const int col = n0 + wn * 32 + nt * 8 + 2 * tg;
        float2 bv = *(const float2*)(bias + col);
        #pragma unroll
        for (int mt = 0; mt < 4; mt++) {
            const int row0 = m0 + wm * 64 + mt * 16 + g;
            float2 r0 = {acc[mt][nt][0] + bv.x, acc[mt][nt][1] + bv.y};
            float2 r1 = {acc[mt][nt][2] + bv.x, acc[mt][nt][3] + bv.y};
            *(float2*)(C + (size_t)row0 * N + col)       = r0;
            *(float2*)(C + (size_t)(row0 + 8) * N + col) = r1;
        }
    }
}

// ---------------------------------------------------------------------------
// Causal MQA flash attention: bf16 m16n8k16 mma, 3-mma hi/lo compensation,
// ldmatrix fragment loads, BQ=128 x BK=64, 256 threads (warps 4x2).
// ---------------------------------------------------------------------------
#define PQ2 68
#define PVP 132
#define PSF 68
#define PP2 36

#define OFF_QHI 0
#define OFF_QLO (OFF_QHI + 128*PQ2)
#define OFF_KHI (OFF_QLO + 128*PQ2)
#define OFF_KLO (OFF_KHI + 64*PQ2)
#define OFF_VP  (OFF_KLO + 64*PQ2)
#define OFF_SF  (OFF_VP  + 64*PVP)
#define OFF_PHI (OFF_SF  + 128*PSF)
#define OFF_PLO (OFF_PHI + 128*PP2)
#define OFF_M   (OFF_PLO + 128*PP2)
#define ATTN_U32 (OFF_M + 3*128)
#define ATTN_SMEM_BYTES (ATTN_U32 * 4)   // 211,456 B

__global__ void __launch_bounds__(256) mqa_attn_tc(
    const float* __restrict__ qkv, float* __restrict__ out)
{
    extern __shared__ uint32_t smem_u[];
    uint32_t* Qhi2 = smem_u + OFF_QHI;
    uint32_t* Qlo2 = smem_u + OFF_QLO;
    uint32_t* Khi2 = smem_u + OFF_KHI;
    uint32_t* Klo2 = smem_u + OFF_KLO;
    uint32_t* Vp   = smem_u + OFF_VP;
    float*    Sf   = (float*)(smem_u + OFF_SF);
    uint32_t* Phi2 = smem_u + OFF_PHI;
    uint32_t* Plo2 = smem_u + OFF_PLO;
    float* m_s = (float*)(smem_u + OFF_M);
    float* l_s = m_s + 128;
    float* f_s = l_s + 128;

    const int tid  = threadIdx.x;
    const int warp = tid >> 5, lane = tid & 31;
    const int g = lane >> 2, tg = lane & 3;
    const int wm = warp >> 1, wn = warp & 1;     // 4 x 2 warp grid
    const int qt = gridDim.x - 1 - blockIdx.x;   // heavy blocks first
    const int h = blockIdx.y, b = blockIdx.z;
    const int q0 = qt * 128;

    const float* qbase = qkv + (size_t)b * SEQ * NQKV + h * HD;
    const float* kbase = qkv + (size_t)b * SEQ * NQKV + H;
    const float* vbase = kbase + HD;

    // ldmatrix lane address patterns
    const int sel = lane >> 3, rr = lane & 7;
    const int a_row = (sel & 1) * 8 + rr;      // within 16-row a-tile
    const int a_col = (sel >> 1) * 4;          // u32 col offset
    const int b_row = (sel >> 1) * 8 + rr;     // within 16-row b-group
    const int b_col = (sel & 1) * 4;

    uint32_t qhiA[2], qloA[2], phiA[2], ploA[2];
    #pragma unroll
    for (int mt = 0; mt < 2; mt++) {
        int row = wm * 32 + mt * 16 + a_row;
        qhiA[mt] = sm_addr(Qhi2) + (row * PQ2 + a_col) * 4;
        qloA[mt] = sm_addr(Qlo2) + (row * PQ2 + a_col) * 4;
        phiA[mt] = sm_addr(Phi2) + (row * PP2 + a_col) * 4;
        ploA[mt] = sm_addr(Plo2) + (row * PP2 + a_col) * 4;
    }
    const uint32_t khiA = sm_addr(Khi2) + ((wn * 32 + b_row) * PQ2 + b_col) * 4;
    const uint32_t khiB = khiA + 16 * PQ2 * 4;
    const uint32_t kloA = sm_addr(Klo2) + ((wn * 32 + b_row) * PQ2 + b_col) * 4;
    const uint32_t kloB = kloA + 16 * PQ2 * 4;

    // Load + split Q tile (128 x 128) once
    for (int i = tid; i < 128 * 32; i += 256) {
        int r = i >> 5, c4 = (i & 31) * 4, c2 = (i & 31) * 2;
        float4 v = *(const float4*)(qbase + (size_t)(q0 + r) * NQKV + c4);
        uint32_t h0,l0,h1,l1,h2,l2,h3,l3;
        split_bf16(v.x, h0, l0); split_bf16(v.y, h1, l1);
        split_bf16(v.z, h2, l2); split_bf16(v.w, h3, l3);
        Qhi2[r*PQ2 + c2]     = h0 | (h1 << 16);
        Qhi2[r*PQ2 + c2 + 1] = h2 | (h3 << 16);
        Qlo2[r*PQ2 + c2]     = l0 | (l1 << 16);
        Qlo2[r*PQ2 + c2 + 1] = l2 | (l3 << 16);
    }
    if (tid < 128) { m_s[tid] = -1e30f; l_s[tid] = 0.f; }

    float o[2][8][4];
    #pragma unroll
    for (int mt = 0; mt < 2; mt++)
        #pragma unroll
        for (int nt = 0; nt < 8; nt++)
            #pragma unroll
            for (int c = 0; c < 4; c++) o[mt][nt][c] = 0.f;

    const int nkt = 2 * qt + 2;
    for (int kt = 0; kt < nkt; kt++) {
        const int k0 = kt * 64;
        __syncthreads();   // prior-iteration readers of K/V done
        // load + split K (hd-paired planes) and V (packed word) tiles
        for (int i = tid; i < 64 * 32; i += 256) {
            int r = i >> 5, c4 = (i & 31) * 4, c2 = (i & 31) * 2;
            float4 kv = *(const float4*)(kbase + (size_t)(k0 + r) * NQKV + c4);
            float4 vv = *(const float4*)(vbase + (size_t)(k0 + r) * NQKV + c4);
            uint32_t h0,l0,h1,l1,h2,l2,h3,l3;
            split_bf16(kv.x, h0, l0); split_bf16(kv.y, h1, l1);
            split_bf16(kv.z, h2, l2); split_bf16(kv.w, h3, l3);
            Khi2[r*PQ2 + c2]     = h0 | (h1 << 16);
            Khi2[r*PQ2 + c2 + 1] = h2 | (h3 << 16);
            Klo2[r*PQ2 + c2]     = l0 | (l1 << 16);
            Klo2[r*PQ2 + c2 + 1] = l2 | (l3 << 16);
            split_bf16(vv.x, h0, l0); split_bf16(vv.y, h1, l1);
            split_bf16(vv.z, h2, l2); split_bf16(vv.w, h3, l3);
            Vp[r*PVP + c4    ] = l0 | (h0 << 16);
            Vp[r*PVP + c4 + 1] = l1 | (h1 << 16);
            Vp[r*PVP + c4 + 2] = l2 | (h2 << 16);
            Vp[r*PVP + c4 + 3] = l3 | (h3 << 16);
        }
        __syncthreads();

        // ---- S = Q @ K^T (128x64), warp tile 32x32 ----
        float sacc[2][4][4];
        #pragma unroll
        for (int mt = 0; mt < 2; mt++)
            #pragma unroll
            for (int nt = 0; nt < 4; nt++)
                #pragma unroll
                for (int c = 0; c < 4; c++) sacc[mt][nt][c] = 0.f;

        #pragma unroll
        for (int ks = 0; ks < 8; ks++) {
            const uint32_t koff = ks * 32;   // 8 u32 per k16 step
            uint32_t ah[2][4], al[2][4], bh[8], bl[8];
            ldsm4(ah[0], qhiA[0] + koff);
            ldsm4(ah[1], qhiA[1] + koff);
            ldsm4(al[0], qloA[0] + koff);
            ldsm4(al[1], qloA[1] + koff);
            ldsm4(bh,     khiA + koff);   // (b0,b1) nt0, (b0,b1) nt1
            ldsm4(bh + 4, khiB + koff);   // nt2, nt3
            ldsm4(bl,     kloA + koff);
            ldsm4(bl + 4, kloB + koff);
            #pragma unroll
            for (int mt = 0; mt < 2; mt++)
                #pragma unroll
                for (int nt = 0; nt < 4; nt++) {
                    mma16bf(sacc[mt][nt], ah[mt], bh[2*nt], bh[2*nt+1]);
                    mma16bf(sacc[mt][nt], ah[mt], bl[2*nt], bl[2*nt+1]);
                    mma16bf(sacc[mt][nt], al[mt], bh[2*nt], bh[2*nt+1]);
                }
        }

        // scale + causal mask + store S
        #pragma unroll
        for (int mt = 0; mt < 2; mt++) {
            const int mb = wm * 32 + mt * 16;
            #pragma unroll
            for (int nt = 0; nt < 4; nt++) {
                const int nb = wn * 32 + nt * 8;
                const int c0 = nb + 2 * tg, c1 = c0 + 1;
                const int r0 = mb + g, r1 = mb + g + 8;
                float s00 = sacc[mt][nt][0] * SCALE;
                float s01 = sacc[mt][nt][1] * SCALE;
                float s10 = sacc[mt][nt][2] * SCALE;
                float s11 = sacc[mt][nt][3] * SCALE;
                if (k0 + c0 > q0 + r0) s00 = -1e30f;
                if (k0 + c1 > q0 + r0) s01 = -1e30f;
                if (k0 + c0 > q0 + r1) s10 = -1e30f;
                if (k0 + c1 > q0 + r1) s11 = -1e30f;
                Sf[r0*PSF + c0] = s00;  Sf[r0*PSF + c1] = s01;
                Sf[r1*PSF + c0] = s10;  Sf[r1*PSF + c1] = s11;
            }
        }
        __syncthreads();

        // ---- online softmax: 2 threads per row ----
        {
            const int row = tid >> 1, sub = tid & 1;
            float* srow = Sf + row*PSF + sub*32;
            float mold = m_s[row];
            float mx = mold;
            #pragma unroll
            for (int c = 0; c < 8; c++) {
                float4 t = *(float4*)&srow[4*c];
                mx = fmaxf(mx, fmaxf(fmaxf(t.x, t.y), fmaxf(t.z, t.w)));
            }
            mx = fmaxf(mx, __shfl_xor_sync(0xffffffffu, mx, 1));
            float sum = 0.f;
            #pragma unroll
            for (int j = 0; j < 8; j++) {
                float4 t = *(float4*)&srow[4*j];
                float p0 = fast_exp(t.x - mx), p1 = fast_exp(t.y - mx);
                float p2 = fast_exp(t.z - mx), p3 = fast_exp(t.w - mx);
                sum += (p0 + p1) + (p2 + p3);
                uint32_t h0,l0,h1,l1;
                split_bf16(p0, h0, l0); split_bf16(p1, h1, l1);
                Phi2[row*PP2 + sub*16 + 2*j]     = h0 | (h1 << 16);
                Plo2[row*PP2 + sub*16 + 2*j]     = l0 | (l1 << 16);
                split_bf16(p2, h0, l0); split_bf16(p3, h1, l1);
                Phi2[row*PP2 + sub*16 + 2*j + 1] = h0 | (h1 << 16);
                Plo2[row*PP2 + sub*16 + 2*j + 1] = l0 | (l1 << 16);
            }
            sum += __shfl_xor_sync(0xffffffffu, sum, 1);
            if (sub == 0) {
                float f = fast_exp(mold - mx);
                l_s[row] = l_s[row] * f + sum;
                m_s[row] = mx;
                f_s[row] = f;
            }
        }
        __syncthreads();

        // ---- O = O*f + P @ V (128x128), warp tile 32x64 ----
        float fr[2][2];
        #pragma unroll
        for (int mt = 0; mt < 2; mt++) {
            const int mb = wm * 32 + mt * 16;
            fr[mt][0] = f_s[mb + g];
            fr[mt][1] = f_s[mb + g + 8];
        }
        #pragma unroll
        for (int mt = 0; mt < 2; mt++)
            #pragma unroll
            for (int nt = 0; nt < 8; nt++) {
                o[mt][nt][0] *= fr[mt][0];  o[mt][nt][1] *= fr[mt][0];
                o[mt][nt][2] *= fr[mt][1];  o[mt][nt][3] *= fr[mt][1];
            }

        #pragma unroll
        for (int ks = 0; ks < 4; ks++) {
            const uint32_t koff = ks * 32;   // 8 u32 per k16 step in P planes
            const int kb = ks * 16;          // k-pos base in V
            uint32_t ah[2][4], al[2][4];
            ldsm4(ah[0], phiA[0] + koff);
            ldsm4(ah[1], phiA[1] + koff);
            ldsm4(al[0], ploA[0] + koff);
            ldsm4(al[1], ploA[1] + koff);
            #pragma unroll
            for (int nt = 0; nt < 8; nt++) {
                const int nb = wn * 64 + nt * 8;
                uint32_t w00 = Vp[(kb + 2*tg    )*PVP + nb + g];
                uint32_t w01 = Vp[(kb + 2*tg + 1)*PVP + nb + g];
                uint32_t w10 = Vp[(kb + 2*tg + 8)*PVP + nb + g];
                uint32_t w11 = Vp[(kb + 2*tg + 9)*PVP + nb + g];
                uint32_t bh0 = prmt(w00, w01, 0x7632u);
                uint32_t bl0 = prmt(w00, w01, 0x5410u);
                uint32_t bh1 = prmt(w10, w11, 0x7632u);
                uint32_t bl1 = prmt(w10, w11, 0x5410u);
                #pragma unroll
                for (int mt = 0; mt < 2; mt++) {
                    mma16bf(o[mt][nt], ah[mt], bh0, bh1);
                    mma16bf(o[mt][nt], ah[mt], bl0, bl1);
                    mma16bf(o[mt][nt], al[mt], bh0, bh1);
                }
            }
        }
    }

    __syncthreads();
    // final write: o / l
    #pragma unroll
    for (int mt = 0; mt < 2; mt++) {
        const int mb = wm * 32 + mt * 16;
        const float inv0 = 1.f / l_s[mb + g];
        const float inv1 = 1.f / l_s[mb + g + 8];
        #pragma unroll
        for (int nt = 0; nt < 8; nt++) {
            const int col = wn * 64 + nt * 8 + 2 * tg;
            size_t row0 = (size_t)(b * SEQ + q0 + mb + g) * H + h * HD + col;
            size_t row1 = (size_t)(b * SEQ + q0 + mb + g + 8) * H + h * HD + col;
            float2 r0 = {o[mt][nt][0] * inv0, o[mt][nt][1] * inv0};
            float2 r1 = {o[mt][nt][2] * inv1, o[mt][nt][3] * inv1};
            *(float2*)(out + row0) = r0;
            *(float2*)(out + row1) = r1;
        }
    }
}

// ---------------------------------------------------------------------------

extern "C" void kernel_launch(void* const* d_in, const int* in_sizes, int n_in,
                              void* d_out, int out_size)
{
    (void)in_sizes; (void)n_in; (void)out_size;
    const float* x     = (const float*)d_in[0];
    const float* Wqkv  = (const float*)d_in[1];
    const float* bqkv  = (const float*)d_in[2];
    const float* Wproj = (const float*)d_in[3];
    const float* bproj = (const float*)d_in[4];
    float* out = (float*)d_out;

    float *qkv_ptr, *attn_ptr;
    cudaGetSymbolAddress((void**)&qkv_ptr, g_qkv);
    cudaGetSymbolAddress((void**)&attn_ptr, g_attn);

    cudaFuncSetAttribute(mqa_attn_tc, cudaFuncAttributeMaxDynamicSharedMemorySize,
                         ATTN_SMEM_BYTES);

    // 1) QKV GEMM (TF32 tensor cores)
    gemm_tf32<NQKV><<<dim3(NQKV / 128, (BATCH * SEQ) / 128), 256>>>(
        x, Wqkv, bqkv, qkv_ptr, H);

    // 2) causal MQA flash attention (bf16 mma + ldmatrix, BQ=128)
    mqa_attn_tc<<<dim3(SEQ / 128, NH, BATCH), 256, ATTN_SMEM_BYTES>>>(qkv_ptr, attn_ptr);

    // 3) proj GEMM (TF32 tensor cores)
    gemm_tf32<H><<<dim3(H / 128, (BATCH * SEQ) / 128), 256>>>(
        attn_ptr, Wproj, bproj, out, H);
}

// round 7
// speedup vs baseline: 3.1627x; 1.2405x over previous
#include <cuda_runtime.h>
#include <math.h>
#include <stdint.h>

#define H 2048
#define NH 16
#define HD 128
#define SEQ 2048
#define BATCH 2
#define NQKV (H + 2*HD)   // 2304
#define SCALE 0.08838834764831843f  // 1/sqrt(128)

// Scratch (allocation-free rule: __device__ globals)
__device__ float g_qkv[(size_t)BATCH * SEQ * NQKV];   // ~37.7 MB
__device__ float g_attn[(size_t)BATCH * SEQ * H];     // ~33.5 MB

__device__ __forceinline__ uint32_t f2tf32(float x) {
    uint32_t r;
    asm("cvt.rna.tf32.f32 %0, %1;" : "=r"(r) : "f"(x));
    return r;
}
__device__ __forceinline__ void mma8(float* c, uint32_t a0, uint32_t a1,
                                     uint32_t a2, uint32_t a3,
                                     uint32_t b0, uint32_t b1) {
    asm volatile(
        "mma.sync.aligned.m16n8k8.row.col.f32.tf32.tf32.f32 "
        "{%0,%1,%2,%3}, {%4,%5,%6,%7}, {%8,%9}, {%0,%1,%2,%3};"
        : "+f"(c[0]), "+f"(c[1]), "+f"(c[2]), "+f"(c[3])
        : "r"(a0), "r"(a1), "r"(a2), "r"(a3), "r"(b0), "r"(b1));
}

// Fast exp on the FMA pipe (avoids the MUFU throughput floor). x <= 0.
__device__ __forceinline__ float fast_exp(float x) {
    float t = fmaxf(x * 1.4426950408889634f, -126.0f);
    float fl = floorf(t);
    float f = t - fl;
    float p =              1.535336188319500e-4f;
    p = fmaf(p, f, 1.339887440266574e-3f);
    p = fmaf(p, f, 9.618437357674640e-3f);
    p = fmaf(p, f, 5.550332471162809e-2f);
    p = fmaf(p, f, 2.402264791363012e-1f);
    p = fmaf(p, f, 6.931472028550421e-1f);
    p = fmaf(p, f, 1.0f);
    uint32_t sc = ((uint32_t)(int)(fl + 127.0f)) << 23;
    return p * __uint_as_float(sc);
}

// ---------------------------------------------------------------------------
// TF32 tensor-core GEMM with bias (round-3/5 version — stable at ~246us).
// ---------------------------------------------------------------------------
template<int N>
__global__ void __launch_bounds__(256) gemm_tf32(
    const float* __restrict__ A, const float* __restrict__ B,
    const float* __restrict__ bias, float* __restrict__ C, int K)
{
    __shared__ uint32_t As[128][36];
    __shared__ uint32_t Bs[32][136];

    const int tid  = threadIdx.x;
    const int warp = tid >> 5, lane = tid & 31;
    const int wm = warp >> 2, wn = warp & 3;
    const int g  = lane >> 2, tg = lane & 3;
    const int m0 = blockIdx.y * 128;
    const int n0 = blockIdx.x * 128;

    const int ar  = tid >> 3;
    const int ac4 = (tid & 7) * 4;
    const int bc4 = (tid & 31) * 4;
    const int br  = tid >> 5;

    float acc[4][4][4];
    #pragma unroll
    for (int i = 0; i < 4; i++)
        #pragma unroll
        for (int j = 0; j < 4; j++)
            #pragma unroll
            for (int c = 0; c < 4; c++) acc[i][j][c] = 0.f;

    for (int kt = 0; kt < K; kt += 32) {
        __syncthreads();
        #pragma unroll
        for (int i = 0; i < 4; i++) {
            float4 v = *(const float4*)(A + (size_t)(m0 + ar + 32*i) * K + kt + ac4);
            uint4 t = {f2tf32(v.x), f2tf32(v.y), f2tf32(v.z), f2tf32(v.w)};
            *(uint4*)&As[ar + 32*i][ac4] = t;
        }
        #pragma unroll
        for (int i = 0; i < 4; i++) {
            float4 v = *(const float4*)(B + (size_t)(kt + br + 8*i) * N + n0 + bc4);
            uint4 t = {f2tf32(v.x), f2tf32(v.y), f2tf32(v.z), f2tf32(v.w)};
            *(uint4*)&Bs[br + 8*i][bc4] = t;
        }
        __syncthreads();

        #pragma unroll
        for (int ks = 0; ks < 4; ks++) {
            const int kb = ks * 8;
            uint32_t a[4][4], b[4][2];
            #pragma unroll
            for (int mt = 0; mt < 4; mt++) {
                const int mb = wm * 64 + mt * 16;
                a[mt][0] = As[mb + g    ][kb + tg    ];
                a[mt][1] = As[mb + g + 8][kb + tg    ];
                a[mt][2] = As[mb + g    ][kb + tg + 4];
                a[mt][3] = As[mb + g + 8][kb + tg + 4];
            }
            #pragma unroll
            for (int nt = 0; nt < 4; nt++) {
                const int nb = wn * 32 + nt * 8;
                b[nt][0] = Bs[kb + tg    ][nb + g];
                b[nt][1] = Bs[kb + tg + 4][nb + g];
            }
            #pragma unroll
            for (int mt = 0; mt < 4; mt++)
                #pragma unroll
                for (int nt = 0; nt < 4; nt++)
                    mma8(acc[mt][nt], a[mt][0], a[mt][1], a[mt][2], a[mt][3],
                         b[nt][0], b[nt][1]);
        }
    }

    #pragma unroll
    for (int nt = 0; nt < 4; nt++) {
        const int col = n0 + wn * 32 + nt * 8 + 2 * tg;
        float2 bv = *(const float2*)(bias + col);
        #pragma unroll
        for (int mt = 0; mt < 4; mt++) {
            const int row0 = m0 + wm * 64 + mt * 16 + g;
            float2 r0 = {acc[mt][nt][0] + bv.x, acc[mt][nt][1] + bv.y};
            float2 r1 = {acc[mt][nt][2] + bv.x, acc[mt][nt][3] + bv.y};
            *(float2*)(C + (size_t)row0 * N + col)       = r0;
            *(float2*)(C + (size_t)(row0 + 8) * N + col) = r1;
        }
    }
}

// ---------------------------------------------------------------------------
// Causal MQA flash attention: single-pass TF32 m16n8k8 (no hi/lo splits).
// BQ=128, BK=64, 256 threads (warps 4x2).
// Smem strides (u32): Q/K 132 (==4 mod 32), V 136 (==8), S/P 68 (==4):
// all fragment-load lane patterns cover 32 banks exactly once.
// ---------------------------------------------------------------------------
#define PQ 132
#define PV 136
#define PS 68

#define OFF_Q 0
#define OFF_K (OFF_Q + 128*PQ)
#define OFF_V (OFF_K + 64*PQ)
#define OFF_S (OFF_V + 64*PV)
#define OFF_M (OFF_S + 128*PS)
#define ATTN_U32 (OFF_M + 3*128)
#define ATTN_SMEM_BYTES (ATTN_U32 * 4)    // 172,544 B

__global__ void __launch_bounds__(256) mqa_attn_tf32(
    const float* __restrict__ qkv, float* __restrict__ out)
{
    extern __shared__ uint32_t smem_u[];
    uint32_t* Qs = smem_u + OFF_Q;
    uint32_t* Ks = smem_u + OFF_K;
    uint32_t* Vs = smem_u + OFF_V;
    float*    Sf = (float*)(smem_u + OFF_S);
    uint32_t* Su = smem_u + OFF_S;           // same buffer as tf32 after softmax
    float* m_s = (float*)(smem_u + OFF_M);
    float* l_s = m_s + 128;
    float* f_s = l_s + 128;

    const int tid  = threadIdx.x;
    const int warp = tid >> 5, lane = tid & 31;
    const int g = lane >> 2, tg = lane & 3;
    const int wm = warp >> 1, wn = warp & 1;     // 4 x 2 warp grid
    const int qt = gridDim.x - 1 - blockIdx.x;   // heavy blocks first
    const int h = blockIdx.y, b = blockIdx.z;
    const int q0 = qt * 128;

    const float* qbase = qkv + (size_t)b * SEQ * NQKV + h * HD;
    const float* kbase = qkv + (size_t)b * SEQ * NQKV + H;
    const float* vbase = kbase + HD;

    // Load Q tile (128 x 128) once, converted to tf32
    for (int i = tid; i < 128 * 32; i += 256) {
        int r = i >> 5, c4 = (i & 31) * 4;
        float4 v = *(const float4*)(qbase + (size_t)(q0 + r) * NQKV + c4);
        Qs[r*PQ + c4    ] = f2tf32(v.x);
        Qs[r*PQ + c4 + 1] = f2tf32(v.y);
        Qs[r*PQ + c4 + 2] = f2tf32(v.z);
        Qs[r*PQ + c4 + 3] = f2tf32(v.w);
    }
    if (tid < 128) { m_s[tid] = -1e30f; l_s[tid] = 0.f; }

    float o[2][8][4];
    #pragma unroll
    for (int mt = 0; mt < 2; mt++)
        #pragma unroll
        for (int nt = 0; nt < 8; nt++)
            #pragma unroll
            for (int c = 0; c < 4; c++) o[mt][nt][c] = 0.f;

    const int nkt = 2 * qt + 2;
    for (int kt = 0; kt < nkt; kt++) {
        const int k0 = kt * 64;
        __syncthreads();   // prior-iteration readers of K/V done
        for (int i = tid; i < 64 * 32; i += 256) {
            int r = i >> 5, c4 = (i & 31) * 4;
            float4 kv = *(const float4*)(kbase + (size_t)(k0 + r) * NQKV + c4);
            float4 vv = *(const float4*)(vbase + (size_t)(k0 + r) * NQKV + c4);
            Ks[r*PQ + c4    ] = f2tf32(kv.x);
            Ks[r*PQ + c4 + 1] = f2tf32(kv.y);
            Ks[r*PQ + c4 + 2] = f2tf32(kv.z);
            Ks[r*PQ + c4 + 3] = f2tf32(kv.w);
            Vs[r*PV + c4    ] = f2tf32(vv.x);
            Vs[r*PV + c4 + 1] = f2tf32(vv.y);
            Vs[r*PV + c4 + 2] = f2tf32(vv.z);
            Vs[r*PV + c4 + 3] = f2tf32(vv.w);
        }
        __syncthreads();

        // ---- S = Q @ K^T (128x64), warp tile 32x32, 16 k8-steps ----
        float sacc[2][4][4];
        #pragma unroll
        for (int mt = 0; mt < 2; mt++)
            #pragma unroll
            for (int nt = 0; nt < 4; nt++)
                #pragma unroll
                for (int c = 0; c < 4; c++) sacc[mt][nt][c] = 0.f;

        #pragma unroll
        for (int ks = 0; ks < 16; ks++) {
            const int kb = ks * 8;
            uint32_t a[2][4], bb[4][2];
            #pragma unroll
            for (int mt = 0; mt < 2; mt++) {
                const int mb = wm * 32 + mt * 16;
                a[mt][0] = Qs[(mb + g    )*PQ + kb + tg    ];
                a[mt][1] = Qs[(mb + g + 8)*PQ + kb + tg    ];
                a[mt][2] = Qs[(mb + g    )*PQ + kb + tg + 4];
                a[mt][3] = Qs[(mb + g + 8)*PQ + kb + tg + 4];
            }
            #pragma unroll
            for (int nt = 0; nt < 4; nt++) {
                const int nb = wn * 32 + nt * 8;
                bb[nt][0] = Ks[(nb + g)*PQ + kb + tg    ];
                bb[nt][1] = Ks[(nb + g)*PQ + kb + tg + 4];
            }
            #pragma unroll
            for (int mt = 0; mt < 2; mt++)
                #pragma unroll
                for (int nt = 0; nt < 4; nt++)
                    mma8(sacc[mt][nt], a[mt][0], a[mt][1], a[mt][2], a[mt][3],
                         bb[nt][0], bb[nt][1]);
        }

        // scale + causal mask + store S (fp32)
        #pragma unroll
        for (int mt = 0; mt < 2; mt++) {
            const int mb = wm * 32 + mt * 16;
            #pragma unroll
            for (int nt = 0; nt < 4; nt++) {
                const int nb = wn * 32 + nt * 8;
                const int c0 = nb + 2 * tg, c1 = c0 + 1;
                const int r0 = mb + g, r1 = mb + g + 8;
                float s00 = sacc[mt][nt][0] * SCALE;
                float s01 = sacc[mt][nt][1] * SCALE;
                float s10 = sacc[mt][nt][2] * SCALE;
                float s11 = sacc[mt][nt][3] * SCALE;
                if (k0 + c0 > q0 + r0) s00 = -1e30f;
                if (k0 + c1 > q0 + r0) s01 = -1e30f;
                if (k0 + c0 > q0 + r1) s10 = -1e30f;
                if (k0 + c1 > q0 + r1) s11 = -1e30f;
                Sf[r0*PS + c0] = s00;  Sf[r0*PS + c1] = s01;
                Sf[r1*PS + c0] = s10;  Sf[r1*PS + c1] = s11;
            }
        }
        __syncthreads();

        // ---- online softmax: 2 threads/row; P written back as tf32 ----
        {
            const int row = tid >> 1, sub = tid & 1;
            float* srow = Sf + row*PS + sub*32;
            uint32_t* urow = Su + row*PS + sub*32;
            float mold = m_s[row];
            float mx = mold;
            #pragma unroll
            for (int c = 0; c < 8; c++) {
                float4 t = *(float4*)&srow[4*c];
                mx = fmaxf(mx, fmaxf(fmaxf(t.x, t.y), fmaxf(t.z, t.w)));
            }
            mx = fmaxf(mx, __shfl_xor_sync(0xffffffffu, mx, 1));
            float sum = 0.f;
            #pragma unroll
            for (int j = 0; j < 8; j++) {
                float4 t = *(float4*)&srow[4*j];
                float p0 = fast_exp(t.x - mx), p1 = fast_exp(t.y - mx);
                float p2 = fast_exp(t.z - mx), p3 = fast_exp(t.w - mx);
                sum += (p0 + p1) + (p2 + p3);
                uint4 u = {f2tf32(p0), f2tf32(p1), f2tf32(p2), f2tf32(p3)};
                *(uint4*)&urow[4*j] = u;
            }
            sum += __shfl_xor_sync(0xffffffffu, sum, 1);
            if (sub == 0) {
                float f = fast_exp(mold - mx);
                l_s[row] = l_s[row] * f + sum;
                m_s[row] = mx;
                f_s[row] = f;
            }
        }
        __syncthreads();

        // ---- O = O*f + P @ V (128x128), warp tile 32x64, 8 k8-steps ----
        float fr[2][2];
        #pragma unroll
        for (int mt = 0; mt < 2; mt++) {
            const int mb = wm * 32 + mt * 16;
            fr[mt][0] = f_s[mb + g];
            fr[mt][1] = f_s[mb + g + 8];
        }
        #pragma unroll
        for (int mt = 0; mt < 2; mt++)
            #pragma unroll
            for (int nt = 0; nt < 8; nt++) {
                o[mt][nt][0] *= fr[mt][0];  o[mt][nt][1] *= fr[mt][0];
                o[mt][nt][2] *= fr[mt][1];  o[mt][nt][3] *= fr[mt][1];
            }

        #pragma unroll
        for (int ks = 0; ks < 8; ks++) {
            const int kb = ks * 8;
            uint32_t a[2][4];
            #pragma unroll
            for (int mt = 0; mt < 2; mt++) {
                const int mb = wm * 32 + mt * 16;
                a[mt][0] = Su[(mb + g    )*PS + kb + tg    ];
                a[mt][1] = Su[(mb + g + 8)*PS + kb + tg    ];
                a[mt][2] = Su[(mb + g    )*PS + kb + tg + 4];
                a[mt][3] = Su[(mb + g + 8)*PS + kb + tg + 4];
            }
            #pragma unroll
            for (int nt = 0; nt < 8; nt++) {
                const int nb = wn * 64 + nt * 8;
                uint32_t b0 = Vs[(kb + tg    )*PV + nb + g];
                uint32_t b1 = Vs[(kb + tg + 4)*PV + nb + g];
                #pragma unroll
                for (int mt = 0; mt < 2; mt++)
                    mma8(o[mt][nt], a[mt][0], a[mt][1], a[mt][2], a[mt][3], b0, b1);
            }
        }
    }

    __syncthreads();
    // final write: o / l
    #pragma unroll
    for (int mt = 0; mt < 2; mt++) {
        const int mb = wm * 32 + mt * 16;
        const float inv0 = 1.f / l_s[mb + g];
        const float inv1 = 1.f / l_s[mb + g + 8];
        #pragma unroll
        for (int nt = 0; nt < 8; nt++) {
            const int col = wn * 64 + nt * 8 + 2 * tg;
            size_t row0 = (size_t)(b * SEQ + q0 + mb + g) * H + h * HD + col;
            size_t row1 = (size_t)(b * SEQ + q0 + mb + g + 8) * H + h * HD + col;
            float2 r0 = {o[mt][nt][0] * inv0, o[mt][nt][1] * inv0};
            float2 r1 = {o[mt][nt][2] * inv1, o[mt][nt][3] * inv1};
            *(float2*)(out + row0) = r0;
            *(float2*)(out + row1) = r1;
        }
    }
}

// ---------------------------------------------------------------------------

extern "C" void kernel_launch(void* const* d_in, const int* in_sizes, int n_in,
                              void* d_out, int out_size)
{
    (void)in_sizes; (void)n_in; (void)out_size;
    const float* x     = (const float*)d_in[0];
    const float* Wqkv  = (const float*)d_in[1];
    const float* bqkv  = (const float*)d_in[2];
    const float* Wproj = (const float*)d_in[3];
    const float* bproj = (const float*)d_in[4];
    float* out = (float*)d_out;

    float *qkv_ptr, *attn_ptr;
    cudaGetSymbolAddress((void**)&qkv_ptr, g_qkv);
    cudaGetSymbolAddress((void**)&attn_ptr, g_attn);

    cudaFuncSetAttribute(mqa_attn_tf32, cudaFuncAttributeMaxDynamicSharedMemorySize,
                         ATTN_SMEM_BYTES);

    // 1) QKV GEMM (TF32 tensor cores)
    gemm_tf32<NQKV><<<dim3(NQKV / 128, (BATCH * SEQ) / 128), 256>>>(
        x, Wqkv, bqkv, qkv_ptr, H);

    // 2) causal MQA flash attention (single-pass TF32 mma)
    mqa_attn_tf32<<<dim3(SEQ / 128, NH, BATCH), 256, ATTN_SMEM_BYTES>>>(qkv_ptr, attn_ptr);

    // 3) proj GEMM (TF32 tensor cores)
    gemm_tf32<H><<<dim3(H / 128, (BATCH * SEQ) / 128), 256>>>(
        attn_ptr, Wproj, bproj, out, H);
}